// round 1
// baseline (speedup 1.0000x reference)
#include <cuda_runtime.h>

#define NEG_INF_F (-1000000.0f)

// Problem shape (fixed by setup_inputs)
constexpr int Bdim = 256;
constexpr int Hdim = 512;
constexpr int SQ   = 256;
constexpr int SP   = 256;
constexpr int TQ   = 64;   // q rows per block

// Shared memory layout (floats):
//   att   [64][256]                      : 16384 floats (64 KB)
//   scratch (aliased):
//     phase1: As[16][64] + Bs[16][256]   : 1024 + 4096 = 5120 floats
//     phase2: Bt[64][68] + Qts[64][68]   : 4352 + 4352 = 8704 floats
//   pmneg [256]                          : 256 floats
constexpr int SMEM_ATT     = 0;
constexpr int SMEM_SCRATCH = 64 * 256;          // 16384
constexpr int SCRATCH_FLTS = 64 * 68 * 2;       // 8704
constexpr int SMEM_PMNEG   = SMEM_SCRATCH + SCRATCH_FLTS;
constexpr int SMEM_TOTAL_F = SMEM_PMNEG + 256;  // 25344 floats
constexpr int SMEM_BYTES   = SMEM_TOTAL_F * 4;  // 101376 bytes

__global__ void __launch_bounds__(256, 2)
rmlstm_fused_kernel(const float* __restrict__ Q,   // (B, H, Sq)
                    const float* __restrict__ P,   // (B, H, Sp)
                    const int*   __restrict__ qm,  // (B, Sq)
                    const int*   __restrict__ pm,  // (B, Sp)
                    float*       __restrict__ out) // (B, Sq, 4H)
{
    extern __shared__ float smem[];
    float* att     = smem + SMEM_ATT;      // [64][256]
    float* scratch = smem + SMEM_SCRATCH;
    float* pmneg   = smem + SMEM_PMNEG;    // [256]

    const int tid = threadIdx.x;
    const int b   = blockIdx.x >> 2;           // Sq / TQ = 4 tiles
    const int q0  = (blockIdx.x & 3) * TQ;

    const float* Qb = Q + (size_t)b * Hdim * SQ;
    const float* Pb = P + (size_t)b * Hdim * SP;

    // p-mask -> additive bias
    pmneg[tid] = pm[b * SP + tid] ? NEG_INF_F : 0.0f;

    // ======================= Phase 1: sim = Q^T @ P =======================
    // C (64 x 256) = sum_h Q[h][q] * P[h][p]
    float* As = scratch;             // [16][64]   As[k][m] = Q[k0+k][q0+m]
    float* Bs = scratch + 16 * 64;   // [16][256]  Bs[k][n] = P[k0+k][n]

    const int tx = tid & 31;   // n-direction lane
    const int ty = tid >> 5;   // m-direction (0..7) -> rows ty*8 .. ty*8+7

    float acc[8][8];
#pragma unroll
    for (int i = 0; i < 8; i++)
#pragma unroll
        for (int j = 0; j < 8; j++) acc[i][j] = 0.0f;

    for (int k0 = 0; k0 < Hdim; k0 += 16) {
        __syncthreads();
        // Load As: 1024 floats, one float4 per thread
        {
            int idx = tid * 4;
            int kk = idx >> 6, mm = idx & 63;
            float4 v = *reinterpret_cast<const float4*>(&Qb[(size_t)(k0 + kk) * SQ + q0 + mm]);
            *reinterpret_cast<float4*>(&As[kk * 64 + mm]) = v;
        }
        // Load Bs: 4096 floats, four float4 per thread
#pragma unroll
        for (int c = 0; c < 4; c++) {
            int idx = c * 1024 + tid * 4;
            int kk = idx >> 8, nn = idx & 255;
            float4 v = *reinterpret_cast<const float4*>(&Pb[(size_t)(k0 + kk) * SP + nn]);
            *reinterpret_cast<float4*>(&Bs[kk * 256 + nn]) = v;
        }
        __syncthreads();

#pragma unroll
        for (int k = 0; k < 16; k++) {
            float a[8], bb[8];
#pragma unroll
            for (int i = 0; i < 8; i++) a[i] = As[k * 64 + ty * 8 + i];        // broadcast
#pragma unroll
            for (int j = 0; j < 8; j++) bb[j] = Bs[k * 256 + tx + j * 32];     // conflict-free
#pragma unroll
            for (int i = 0; i < 8; i++)
#pragma unroll
                for (int j = 0; j < 8; j++)
                    acc[i][j] = fmaf(a[i], bb[j], acc[i][j]);
        }
    }

    // Store sim tile to shared
#pragma unroll
    for (int i = 0; i < 8; i++)
#pragma unroll
        for (int j = 0; j < 8; j++)
            att[(ty * 8 + i) * 256 + tx + j * 32] = acc[i][j];
    __syncthreads();

    // ======================= Softmax over p (row-wise) ====================
    {
        const int warp = tid >> 5, lane = tid & 31;
#pragma unroll 1
        for (int r = warp; r < TQ; r += 8) {
            const float qmv = qm[b * SQ + q0 + r] ? 1.0f : 0.0f;
            float x[8];
            float mx = -3.4e38f;
#pragma unroll
            for (int u = 0; u < 8; u++) {
                float v = att[r * 256 + lane + u * 32] + qmv * pmneg[lane + u * 32];
                x[u] = v;
                mx = fmaxf(mx, v);
            }
#pragma unroll
            for (int o = 16; o > 0; o >>= 1) mx = fmaxf(mx, __shfl_xor_sync(0xffffffffu, mx, o));
            float s = 0.0f;
#pragma unroll
            for (int u = 0; u < 8; u++) { x[u] = __expf(x[u] - mx); s += x[u]; }
#pragma unroll
            for (int o = 16; o > 0; o >>= 1) s += __shfl_xor_sync(0xffffffffu, s, o);
            const float inv = 1.0f / s;
#pragma unroll
            for (int u = 0; u < 8; u++) att[r * 256 + lane + u * 32] = x[u] * inv;
        }
    }
    __syncthreads();

    // ============ Phase 2: q_tilda = att @ P^T, fused concat ==============
    // C2 (64 q x 512 h) = sum_p att[q][p] * P[h][p], tiled 64 h at a time.
    float* Bt  = scratch;             // [64][68]  Bt[h][p] = P[h0+h][p0+p]
    float* Qts = scratch + 64 * 68;   // [64][68]  Qts[m][h] = Q[h0+h][q0+m]

    const int tx2 = tid & 15;   // n (h) direction
    const int ty2 = tid >> 4;   // m (q) direction (0..15)

    for (int h0 = 0; h0 < Hdim; h0 += 64) {
        float acc2[4][4];
#pragma unroll
        for (int i = 0; i < 4; i++)
#pragma unroll
            for (int j = 0; j < 4; j++) acc2[i][j] = 0.0f;

        for (int p0 = 0; p0 < SP; p0 += 64) {
            __syncthreads();
            // Load Bt: 64 rows of 64 contiguous floats from P
#pragma unroll
            for (int c = 0; c < 4; c++) {
                int idx = c * 1024 + tid * 4;
                int hh = idx >> 6, pp = idx & 63;
                float4 v = *reinterpret_cast<const float4*>(&Pb[(size_t)(h0 + hh) * SP + p0 + pp]);
                *reinterpret_cast<float4*>(&Bt[hh * 68 + pp]) = v;
            }
            __syncthreads();

#pragma unroll 8
            for (int k = 0; k < 64; k++) {
                float a[4], bb[4];
#pragma unroll
                for (int i = 0; i < 4; i++) a[i] = att[(ty2 + i * 16) * 256 + p0 + k];
#pragma unroll
                for (int j = 0; j < 4; j++) bb[j] = Bt[(tx2 + j * 16) * 68 + k];
#pragma unroll
                for (int i = 0; i < 4; i++)
#pragma unroll
                    for (int j = 0; j < 4; j++)
                        acc2[i][j] = fmaf(a[i], bb[j], acc2[i][j]);
            }
        }

        // Stage transposed Q tile: Qts[m][h] = Q[h0+h][q0+m]
        __syncthreads();
#pragma unroll
        for (int c = 0; c < 4; c++) {
            int idx = c * 1024 + tid * 4;
            int hh = idx >> 6, mm = idx & 63;
            float4 v = *reinterpret_cast<const float4*>(&Qb[(size_t)(h0 + hh) * SQ + q0 + mm]);
            Qts[(mm + 0) * 68 + hh] = v.x;
            Qts[(mm + 1) * 68 + hh] = v.y;
            Qts[(mm + 2) * 68 + hh] = v.z;
            Qts[(mm + 3) * 68 + hh] = v.w;
        }
        __syncthreads();

        // Write the 4-way concat: [q_t, q_tilda, q_t - q_tilda, q_t * q_tilda]
#pragma unroll
        for (int i = 0; i < 4; i++) {
            const int m = ty2 + i * 16;
            float* ob = out + ((size_t)(b * SQ + q0 + m)) * (4 * Hdim) + h0;
#pragma unroll
            for (int j = 0; j < 4; j++) {
                const int h = tx2 + j * 16;
                const float qt = Qts[m * 68 + h];
                const float td = acc2[i][j];
                ob[h]              = qt;
                ob[Hdim + h]       = td;
                ob[2 * Hdim + h]   = qt - td;
                ob[3 * Hdim + h]   = qt * td;
            }
        }
        // next h0 iteration's Bt load syncs before overwriting scratch
    }
}

extern "C" void kernel_launch(void* const* d_in, const int* in_sizes, int n_in,
                              void* d_out, int out_size)
{
    const float* Q  = (const float*)d_in[0];
    const float* P  = (const float*)d_in[1];
    const int*   qm = (const int*)d_in[2];
    const int*   pm = (const int*)d_in[3];
    float*       O  = (float*)d_out;

    cudaFuncSetAttribute(rmlstm_fused_kernel,
                         cudaFuncAttributeMaxDynamicSharedMemorySize, SMEM_BYTES);

    dim3 grid(Bdim * (SQ / TQ));
    dim3 block(256);
    rmlstm_fused_kernel<<<grid, block, SMEM_BYTES>>>(Q, P, qm, pm, O);
}

// round 3
// speedup vs baseline: 1.7282x; 1.7282x over previous
#include <cuda_runtime.h>
#include <cuda_bf16.h>
#include <cstdint>

#define NEG_INF_F (-1000000.0f)

constexpr int Hh = 512, Sn = 256;           // H, Sq=Sp
constexpr int TQ = 128;                     // q rows per CTA

// ---- smem byte offsets ----
constexpr int ATT_HI = 0;                   // [128 m][256 k] bf16, row stride 528
constexpr int ATT_LO = 67584;
constexpr int SCR    = 135168;              // 69632-byte aliased scratch
//   phase1 (double buffered, 25600/buf): A_hi(16x272) A_lo B_hi(16x528) B_lo
constexpr int P1_ALO = 4352, P1_BHI = 8704, P1_BLO = 17152, P1_BUF = 25600;
//   phase2: B2_hi(64x528)=33792, B2_lo
constexpr int B2_LO_OFF = 33792;
//   epilogue: SD2 float[128][68]=34816, SQT
constexpr int SQT_OFF = 34816;
constexpr int PMNEG = 204800;               // float[256]
constexpr int QMV   = 205824;               // float[128]
constexpr int RED1  = 206336;               // float[128][4]
constexpr int RED2  = 208384;               // float[128][4]
constexpr int SMEM_BYTES = 210432;

__device__ __forceinline__ uint32_t smem_u32(const void* p) {
    uint32_t a;
    asm("{ .reg .u64 t; cvta.to.shared.u64 t, %1; cvt.u32.u64 %0, t; }" : "=r"(a) : "l"(p));
    return a;
}
__device__ __forceinline__ void ldsm4(uint32_t a[4], uint32_t addr) {
    asm volatile("ldmatrix.sync.aligned.m8n8.x4.shared.b16 {%0,%1,%2,%3}, [%4];"
                 : "=r"(a[0]), "=r"(a[1]), "=r"(a[2]), "=r"(a[3]) : "r"(addr));
}
__device__ __forceinline__ void ldsm4t(uint32_t a[4], uint32_t addr) {
    asm volatile("ldmatrix.sync.aligned.m8n8.x4.trans.shared.b16 {%0,%1,%2,%3}, [%4];"
                 : "=r"(a[0]), "=r"(a[1]), "=r"(a[2]), "=r"(a[3]) : "r"(addr));
}
__device__ __forceinline__ void mma16816(float d[4], const uint32_t a[4],
                                         uint32_t b0, uint32_t b1) {
    asm volatile("mma.sync.aligned.m16n8k16.row.col.f32.bf16.bf16.f32 "
                 "{%0,%1,%2,%3}, {%4,%5,%6,%7}, {%8,%9}, {%0,%1,%2,%3};"
                 : "+f"(d[0]), "+f"(d[1]), "+f"(d[2]), "+f"(d[3])
                 : "r"(a[0]), "r"(a[1]), "r"(a[2]), "r"(a[3]), "r"(b0), "r"(b1));
}
__device__ __forceinline__ void split4(float4 v, uint2& hi, uint2& lo) {
    __nv_bfloat162 h01 = __float22bfloat162_rn(make_float2(v.x, v.y));
    __nv_bfloat162 h23 = __float22bfloat162_rn(make_float2(v.z, v.w));
    float2 f01 = __bfloat1622float2(h01), f23 = __bfloat1622float2(h23);
    __nv_bfloat162 l01 = __float22bfloat162_rn(make_float2(v.x - f01.x, v.y - f01.y));
    __nv_bfloat162 l23 = __float22bfloat162_rn(make_float2(v.z - f23.x, v.w - f23.y));
    hi.x = *reinterpret_cast<uint32_t*>(&h01); hi.y = *reinterpret_cast<uint32_t*>(&h23);
    lo.x = *reinterpret_cast<uint32_t*>(&l01); lo.y = *reinterpret_cast<uint32_t*>(&l23);
}
__device__ __forceinline__ uint32_t pack2(float v0, float v1) {
    __nv_bfloat162 h = __float22bfloat162_rn(make_float2(v0, v1));
    return *reinterpret_cast<uint32_t*>(&h);
}
__device__ __forceinline__ uint32_t pack2res(float v0, float v1, uint32_t hiw) {
    __nv_bfloat162 h = *reinterpret_cast<__nv_bfloat162*>(&hiw);
    float2 f = __bfloat1622float2(h);
    __nv_bfloat162 l = __float22bfloat162_rn(make_float2(v0 - f.x, v1 - f.y));
    return *reinterpret_cast<uint32_t*>(&l);
}

__global__ void __launch_bounds__(256, 1)
rml_mma_kernel(const float* __restrict__ Q, const float* __restrict__ P,
               const int* __restrict__ qmask, const int* __restrict__ pmask,
               float* __restrict__ out)
{
    extern __shared__ char smb[];
    const uint32_t sb = smem_u32(smb);
    float* smf = reinterpret_cast<float*>(smb);

    const int tid = threadIdx.x, lane = tid & 31, wid = tid >> 5;
    const int g = lane >> 2, c2 = lane & 3, sel = lane >> 3, r8 = lane & 7;
    const int wm = wid >> 2, wn = wid & 3;
    const int R0 = wm * 64, C0 = wn * 64;
    const int b = blockIdx.x >> 1, q0 = (blockIdx.x & 1) * TQ;

    const float* Qb = Q + (size_t)b * Hh * Sn;
    const float* Pb = P + (size_t)b * Hh * Sn;

    smf[PMNEG/4 + tid] = pmask[b * Sn + tid] ? NEG_INF_F : 0.0f;
    if (tid < 128) smf[QMV/4 + tid] = qmask[b * Sn + q0 + tid] ? 1.0f : 0.0f;

    // lane-constant ldmatrix offsets
    const int arowA = (sel >> 1) * 8 + r8, acol8 = (sel & 1) * 8;   // phase1 A (trans, [k][m])
    const int browB = (sel & 1) * 8 + r8, bcol8 = (sel >> 1) * 8;   // phase1 B (trans, [k][n])
    const int p2Ar  = (sel & 1) * 8 + r8, p2Ac8 = (sel >> 1) * 8;   // phase2 A ([m][k])
    const int p2Br  = (sel >> 1) * 8 + r8, p2Bc8 = (sel & 1) * 8;   // phase2 B ([n][k])

    float acc[4][8][4];
#pragma unroll
    for (int a = 0; a < 4; a++)
#pragma unroll
        for (int c = 0; c < 8; c++)
#pragma unroll
            for (int j = 0; j < 4; j++) acc[a][c][j] = 0.0f;

    // ---------------- Phase 1: sim = Q^T @ P (regs) -----------------------
    // stage chunk 0
    {
        const uint32_t ba = sb + SCR;
#pragma unroll
        for (int i = 0; i < 2; i++) {
            int fl = i * 256 + tid, k = fl >> 5, u = fl & 31;
            float4 v = *(const float4*)(Qb + (size_t)k * Sn + q0 + 4 * u);
            uint2 hi, lo; split4(v, hi, lo);
            *(uint2*)(smb + SCR + k * 272 + u * 8) = hi;
            *(uint2*)(smb + SCR + P1_ALO + k * 272 + u * 8) = lo;
        }
#pragma unroll
        for (int i = 0; i < 4; i++) {
            int fl = i * 256 + tid, k = fl >> 6, u = fl & 63;
            float4 v = *(const float4*)(Pb + (size_t)k * Sn + 4 * u);
            uint2 hi, lo; split4(v, hi, lo);
            *(uint2*)(smb + SCR + P1_BHI + k * 272 * 0 + k * 528 + u * 8) = hi;
            *(uint2*)(smb + SCR + P1_BLO + k * 528 + u * 8) = lo;
        }
        (void)ba;
    }
    __syncthreads();

    for (int kc = 0; kc < 32; ++kc) {
        const int cur = kc & 1;
        // prefetch next chunk into regs
        float4 va[2], vb[4];
        if (kc < 31) {
            const int h0n = (kc + 1) * 16;
#pragma unroll
            for (int i = 0; i < 2; i++) {
                int fl = i * 256 + tid, k = fl >> 5, u = fl & 31;
                va[i] = *(const float4*)(Qb + (size_t)(h0n + k) * Sn + q0 + 4 * u);
            }
#pragma unroll
            for (int i = 0; i < 4; i++) {
                int fl = i * 256 + tid, k = fl >> 6, u = fl & 63;
                vb[i] = *(const float4*)(Pb + (size_t)(h0n + k) * Sn + 4 * u);
            }
        }

        // MMA on current buffer
        const uint32_t abh = sb + SCR + cur * P1_BUF;
        const uint32_t abl = abh + P1_ALO;
        const uint32_t bbh = sb + SCR + cur * P1_BUF + P1_BHI;
        const uint32_t bbl = sb + SCR + cur * P1_BUF + P1_BLO;

        uint32_t ah[4][4], al[4][4];
#pragma unroll
        for (int mf = 0; mf < 4; mf++) {
            uint32_t co = (uint32_t)((R0 + mf * 16 + acol8) * 2 + arowA * 272);
            ldsm4(ah[mf], 0);  // placeholder avoided below
            (void)co;
        }
        // (re-load properly; above kept minimal — real loads:)
#pragma unroll
        for (int mf = 0; mf < 4; mf++) {
            uint32_t off = (uint32_t)(arowA * 272 + (R0 + mf * 16 + acol8) * 2);
            ldsm4t(ah[mf], abh + off);
            ldsm4t(al[mf], abl + off);
        }
#pragma unroll
        for (int nh = 0; nh < 4; nh++) {
            uint32_t off = (uint32_t)(browB * 528 + (C0 + nh * 16 + bcol8) * 2);
            uint32_t bh[4], bl[4];
            ldsm4t(bh, bbh + off);
            ldsm4t(bl, bbl + off);
#pragma unroll
            for (int mf = 0; mf < 4; mf++) {
                mma16816(acc[mf][2*nh],   ah[mf], bh[0], bh[1]);
                mma16816(acc[mf][2*nh],   ah[mf], bl[0], bl[1]);
                mma16816(acc[mf][2*nh],   al[mf], bh[0], bh[1]);
                mma16816(acc[mf][2*nh+1], ah[mf], bh[2], bh[3]);
                mma16816(acc[mf][2*nh+1], ah[mf], bl[2], bl[3]);
                mma16816(acc[mf][2*nh+1], al[mf], bh[2], bh[3]);
            }
        }

        // store prefetched chunk
        if (kc < 31) {
            const int nxt = cur ^ 1;
            const uint32_t base = SCR + nxt * P1_BUF;
#pragma unroll
            for (int i = 0; i < 2; i++) {
                int fl = i * 256 + tid, k = fl >> 5, u = fl & 31;
                uint2 hi, lo; split4(va[i], hi, lo);
                *(uint2*)(smb + base + k * 272 + u * 8) = hi;
                *(uint2*)(smb + base + P1_ALO + k * 272 + u * 8) = lo;
            }
#pragma unroll
            for (int i = 0; i < 4; i++) {
                int fl = i * 256 + tid, k = fl >> 6, u = fl & 63;
                uint2 hi, lo; split4(vb[i], hi, lo);
                *(uint2*)(smb + base + P1_BHI + k * 528 + u * 8) = hi;
                *(uint2*)(smb + base + P1_BLO + k * 528 + u * 8) = lo;
            }
        }
        __syncthreads();
    }

    // ---------------- Softmax (registers + small smem reduce) -------------
    float pmb[8][2], qv[4][2];
#pragma unroll
    for (int nf = 0; nf < 8; nf++) {
        pmb[nf][0] = smf[PMNEG/4 + C0 + nf * 8 + 2 * c2];
        pmb[nf][1] = smf[PMNEG/4 + C0 + nf * 8 + 2 * c2 + 1];
    }
#pragma unroll
    for (int mf = 0; mf < 4; mf++) {
        qv[mf][0] = smf[QMV/4 + R0 + mf * 16 + g];
        qv[mf][1] = smf[QMV/4 + R0 + mf * 16 + g + 8];
    }
    float mx[4][2];
#pragma unroll
    for (int mf = 0; mf < 4; mf++)
#pragma unroll
        for (int h = 0; h < 2; h++) {
            float m = -3.4e38f;
#pragma unroll
            for (int nf = 0; nf < 8; nf++)
#pragma unroll
                for (int p = 0; p < 2; p++) {
                    float x = acc[mf][nf][2*h + p] + qv[mf][h] * pmb[nf][p];
                    acc[mf][nf][2*h + p] = x;
                    m = fmaxf(m, x);
                }
            m = fmaxf(m, __shfl_xor_sync(0xffffffffu, m, 1));
            m = fmaxf(m, __shfl_xor_sync(0xffffffffu, m, 2));
            mx[mf][h] = m;
            if (c2 == 0) smf[RED1/4 + (R0 + mf * 16 + g + 8 * h) * 4 + wn] = m;
        }
    __syncthreads();
    float sm[4][2];
#pragma unroll
    for (int mf = 0; mf < 4; mf++)
#pragma unroll
        for (int h = 0; h < 2; h++) {
            const int row = R0 + mf * 16 + g + 8 * h;
            float m = fmaxf(fmaxf(smf[RED1/4 + row*4], smf[RED1/4 + row*4 + 1]),
                            fmaxf(smf[RED1/4 + row*4 + 2], smf[RED1/4 + row*4 + 3]));
            mx[mf][h] = m;
            float s = 0.0f;
#pragma unroll
            for (int nf = 0; nf < 8; nf++)
#pragma unroll
                for (int p = 0; p < 2; p++) {
                    float e = __expf(acc[mf][nf][2*h + p] - m);
                    acc[mf][nf][2*h + p] = e;
                    s += e;
                }
            s += __shfl_xor_sync(0xffffffffu, s, 1);
            s += __shfl_xor_sync(0xffffffffu, s, 2);
            if (c2 == 0) smf[RED2/4 + row * 4 + wn] = s;
            sm[mf][h] = s;
        }
    __syncthreads();
#pragma unroll
    for (int mf = 0; mf < 4; mf++)
#pragma unroll
        for (int h = 0; h < 2; h++) {
            const int row = R0 + mf * 16 + g + 8 * h;
            float s = smf[RED2/4 + row*4] + smf[RED2/4 + row*4 + 1] +
                      smf[RED2/4 + row*4 + 2] + smf[RED2/4 + row*4 + 3];
            const float inv = 1.0f / s;
            (void)sm; (void)mx;
#pragma unroll
            for (int nf = 0; nf < 8; nf++) {
                float v0 = acc[mf][nf][2*h]     * inv;
                float v1 = acc[mf][nf][2*h + 1] * inv;
                uint32_t hiw = pack2(v0, v1);
                uint32_t low = pack2res(v0, v1, hiw);
                uint32_t off = (uint32_t)(row * 528 + (C0 + nf * 8 + 2 * c2) * 2);
                *(uint32_t*)(smb + ATT_HI + off) = hiw;
                *(uint32_t*)(smb + ATT_LO + off) = low;
            }
        }
    __syncthreads();

    // ---------------- Phase 2: q_tilda = att @ P^T + concat ---------------
    const int C2_0 = wn * 16;
    const int j4 = tid & 15, fch = (tid >> 4) & 3, g2 = tid >> 6;
    const int mrow = tid & 127, half = tid >> 7;

    for (int t = 0; t < 8; ++t) {
        const int h0 = t * 64;
        // stage B2 [n=64][k=256] split bf16
#pragma unroll
        for (int i = 0; i < 16; i++) {
            int fl = i * 256 + tid, n = fl >> 6, u = fl & 63;
            float4 v = *(const float4*)(Pb + (size_t)(h0 + n) * Sn + 4 * u);
            uint2 hi, lo; split4(v, hi, lo);
            *(uint2*)(smb + SCR + n * 528 + u * 8) = hi;
            *(uint2*)(smb + SCR + B2_LO_OFF + n * 528 + u * 8) = lo;
        }
        __syncthreads();

        float acc2[4][2][4];
#pragma unroll
        for (int a = 0; a < 4; a++)
#pragma unroll
            for (int c = 0; c < 2; c++)
#pragma unroll
                for (int j = 0; j < 4; j++) acc2[a][c][j] = 0.0f;

        for (int ks = 0; ks < 16; ++ks) {
            const int k0 = ks * 16;
            uint32_t ah2[4][4], al2[4][4];
#pragma unroll
            for (int mf = 0; mf < 4; mf++) {
                uint32_t off = (uint32_t)((R0 + mf * 16 + p2Ar) * 528 + (k0 + p2Ac8) * 2);
                ldsm4(ah2[mf], sb + ATT_HI + off);
                ldsm4(al2[mf], sb + ATT_LO + off);
            }
            uint32_t bh[4], bl[4];
            {
                uint32_t off = (uint32_t)((C2_0 + p2Br) * 528 + (k0 + p2Bc8) * 2);
                ldsm4(bh, sb + SCR + off);
                ldsm4(bl, sb + SCR + B2_LO_OFF + off);
            }
#pragma unroll
            for (int mf = 0; mf < 4; mf++) {
                mma16816(acc2[mf][0], ah2[mf], bh[0], bh[1]);
                mma16816(acc2[mf][0], ah2[mf], bl[0], bl[1]);
                mma16816(acc2[mf][0], al2[mf], bh[0], bh[1]);
                mma16816(acc2[mf][1], ah2[mf], bh[2], bh[3]);
                mma16816(acc2[mf][1], ah2[mf], bl[2], bl[3]);
                mma16816(acc2[mf][1], al2[mf], bh[2], bh[3]);
            }
        }
        __syncthreads();   // B2 consumed; SD2/SQT may overwrite

        // stage D2 + Q^T
#pragma unroll
        for (int mf = 0; mf < 4; mf++)
#pragma unroll
            for (int nf = 0; nf < 2; nf++)
#pragma unroll
                for (int h = 0; h < 2; h++) {
                    const int row = R0 + mf * 16 + g + 8 * h;
                    const int col = C2_0 + nf * 8 + 2 * c2;
                    *(float2*)(smf + SCR/4 + row * 68 + col) =
                        make_float2(acc2[mf][nf][2*h], acc2[mf][nf][2*h + 1]);
                }
#pragma unroll 8
        for (int j = 0; j < 32; j++) {
            const int hh = half * 32 + j;
            smf[SCR/4 + SQT_OFF/4 + mrow * 68 + hh] =
                Qb[(size_t)(h0 + hh) * Sn + q0 + mrow];
        }
        __syncthreads();

        // concat write
#pragma unroll 4
        for (int mp = 0; mp < 32; mp++) {
            const int mm = mp * 4 + g2;
            float4 qt = *(const float4*)(smf + SCR/4 + SQT_OFF/4 + mm * 68 + j4 * 4);
            float4 td = *(const float4*)(smf + SCR/4 + mm * 68 + j4 * 4);
            float4 o;
            if      (fch == 0) o = qt;
            else if (fch == 1) o = td;
            else if (fch == 2) o = make_float4(qt.x - td.x, qt.y - td.y, qt.z - td.z, qt.w - td.w);
            else               o = make_float4(qt.x * td.x, qt.y * td.y, qt.z * td.z, qt.w * td.w);
            *(float4*)(out + ((size_t)(b * Sn + q0 + mm)) * 2048 + fch * 512 + h0 + j4 * 4) = o;
        }
        __syncthreads();
    }
}

extern "C" void kernel_launch(void* const* d_in, const int* in_sizes, int n_in,
                              void* d_out, int out_size)
{
    const float* Q  = (const float*)d_in[0];
    const float* P  = (const float*)d_in[1];
    const int*   qm = (const int*)d_in[2];
    const int*   pm = (const int*)d_in[3];
    float*       O  = (float*)d_out;

    cudaFuncSetAttribute(rml_mma_kernel,
                         cudaFuncAttributeMaxDynamicSharedMemorySize, SMEM_BYTES);

    rml_mma_kernel<<<512, 256, SMEM_BYTES>>>(Q, P, qm, pm, O);
}

// round 4
// speedup vs baseline: 2.1259x; 1.2301x over previous
#include <cuda_runtime.h>
#include <cuda_bf16.h>
#include <cstdint>

#define NEG_INF_F (-1000000.0f)

constexpr int Hh = 512, Sn = 256;           // H, Sq=Sp
constexpr int TQ = 128;                     // q rows per CTA

// ---- smem byte offsets ----
constexpr int ATT_HI = 0;                   // [128 m][256 k] bf16, row stride 528
constexpr int ATT_LO = 67584;
constexpr int SCR    = 135168;              // 69632-byte aliased scratch
constexpr int P1_ALO = 4352, P1_BHI = 8704, P1_BLO = 17152, P1_BUF = 25600;
constexpr int B2_LO_OFF = 33792;
constexpr int SQT_OFF = 34816;
constexpr int PMNEG = 204800;               // float[256]
constexpr int QMV   = 205824;               // float[128]
constexpr int RED1  = 206336;               // float[128][4]
constexpr int RED2  = 208384;               // float[128][4]
constexpr int SMEM_BYTES = 210432;

__device__ __forceinline__ uint32_t smem_u32(const void* p) {
    uint32_t a;
    asm("{ .reg .u64 t; cvta.to.shared.u64 t, %1; cvt.u32.u64 %0, t; }" : "=r"(a) : "l"(p));
    return a;
}
__device__ __forceinline__ void ldsm4(uint32_t a[4], uint32_t addr) {
    asm volatile("ldmatrix.sync.aligned.m8n8.x4.shared.b16 {%0,%1,%2,%3}, [%4];"
                 : "=r"(a[0]), "=r"(a[1]), "=r"(a[2]), "=r"(a[3]) : "r"(addr));
}
__device__ __forceinline__ void ldsm4t(uint32_t a[4], uint32_t addr) {
    asm volatile("ldmatrix.sync.aligned.m8n8.x4.trans.shared.b16 {%0,%1,%2,%3}, [%4];"
                 : "=r"(a[0]), "=r"(a[1]), "=r"(a[2]), "=r"(a[3]) : "r"(addr));
}
__device__ __forceinline__ void mma16816(float d[4], const uint32_t a[4],
                                         uint32_t b0, uint32_t b1) {
    asm volatile("mma.sync.aligned.m16n8k16.row.col.f32.bf16.bf16.f32 "
                 "{%0,%1,%2,%3}, {%4,%5,%6,%7}, {%8,%9}, {%0,%1,%2,%3};"
                 : "+f"(d[0]), "+f"(d[1]), "+f"(d[2]), "+f"(d[3])
                 : "r"(a[0]), "r"(a[1]), "r"(a[2]), "r"(a[3]), "r"(b0), "r"(b1));
}
__device__ __forceinline__ void split4(float4 v, uint2& hi, uint2& lo) {
    __nv_bfloat162 h01 = __float22bfloat162_rn(make_float2(v.x, v.y));
    __nv_bfloat162 h23 = __float22bfloat162_rn(make_float2(v.z, v.w));
    float2 f01 = __bfloat1622float2(h01), f23 = __bfloat1622float2(h23);
    __nv_bfloat162 l01 = __float22bfloat162_rn(make_float2(v.x - f01.x, v.y - f01.y));
    __nv_bfloat162 l23 = __float22bfloat162_rn(make_float2(v.z - f23.x, v.w - f23.y));
    hi.x = *reinterpret_cast<uint32_t*>(&h01); hi.y = *reinterpret_cast<uint32_t*>(&h23);
    lo.x = *reinterpret_cast<uint32_t*>(&l01); lo.y = *reinterpret_cast<uint32_t*>(&l23);
}
__device__ __forceinline__ uint32_t pack2(float v0, float v1) {
    __nv_bfloat162 h = __float22bfloat162_rn(make_float2(v0, v1));
    return *reinterpret_cast<uint32_t*>(&h);
}
__device__ __forceinline__ uint32_t pack2res(float v0, float v1, uint32_t hiw) {
    __nv_bfloat162 h = *reinterpret_cast<__nv_bfloat162*>(&hiw);
    float2 f = __bfloat1622float2(h);
    __nv_bfloat162 l = __float22bfloat162_rn(make_float2(v0 - f.x, v1 - f.y));
    return *reinterpret_cast<uint32_t*>(&l);
}

__global__ void __launch_bounds__(512, 1)
rml_mma_kernel(const float* __restrict__ Q, const float* __restrict__ P,
               const int* __restrict__ qmask, const int* __restrict__ pmask,
               float* __restrict__ out)
{
    extern __shared__ char smb[];
    const uint32_t sb = smem_u32(smb);
    float* smf = reinterpret_cast<float*>(smb);

    const int tid = threadIdx.x, lane = tid & 31, wid = tid >> 5;
    const int g = lane >> 2, c2 = lane & 3, sel = lane >> 3, r8 = lane & 7;
    const int wm = wid >> 2, wn = wid & 3;
    const int R0 = wm * 32, C0 = wn * 64;           // phase1 warp tile 32m x 64n
    const int b = blockIdx.x >> 1, q0 = (blockIdx.x & 1) * TQ;

    const float* Qb = Q + (size_t)b * Hh * Sn;
    const float* Pb = P + (size_t)b * Hh * Sn;

    if (tid < 256) smf[PMNEG/4 + tid] = pmask[b * Sn + tid] ? NEG_INF_F : 0.0f;
    if (tid < 128) smf[QMV/4 + tid] = qmask[b * Sn + q0 + tid] ? 1.0f : 0.0f;

    // lane-constant ldmatrix offsets
    const int arowA = (sel >> 1) * 8 + r8, acol8 = (sel & 1) * 8;   // phase1 A (trans, [k][m])
    const int browB = (sel & 1) * 8 + r8, bcol8 = (sel >> 1) * 8;   // phase1 B (trans, [k][n])
    const int p2Ar  = (sel & 1) * 8 + r8, p2Ac8 = (sel >> 1) * 8;   // phase2 A ([m][k])
    const int p2Br  = (sel >> 1) * 8 + r8, p2Bc8 = (sel & 1) * 8;   // phase2 B ([n][k])

    float acc[2][8][4];
#pragma unroll
    for (int a = 0; a < 2; a++)
#pragma unroll
        for (int c = 0; c < 8; c++)
#pragma unroll
            for (int j = 0; j < 4; j++) acc[a][c][j] = 0.0f;

    // ---------------- Phase 1: sim = Q^T @ P (regs) -----------------------
    // stage chunk 0 (512 threads: 1 float4 Q, 2 float4 P each)
    {
        int k = tid >> 5, u = tid & 31;
        float4 v = *(const float4*)(Qb + (size_t)k * Sn + q0 + 4 * u);
        uint2 hi, lo; split4(v, hi, lo);
        *(uint2*)(smb + SCR + k * 272 + u * 8) = hi;
        *(uint2*)(smb + SCR + P1_ALO + k * 272 + u * 8) = lo;
#pragma unroll
        for (int i = 0; i < 2; i++) {
            int fl = i * 512 + tid, kk = fl >> 6, uu = fl & 63;
            float4 w = *(const float4*)(Pb + (size_t)kk * Sn + 4 * uu);
            uint2 h2, l2; split4(w, h2, l2);
            *(uint2*)(smb + SCR + P1_BHI + kk * 528 + uu * 8) = h2;
            *(uint2*)(smb + SCR + P1_BLO + kk * 528 + uu * 8) = l2;
        }
    }
    __syncthreads();

    for (int kc = 0; kc < 32; ++kc) {
        const int cur = kc & 1;
        // prefetch next chunk into regs
        float4 va, vb[2];
        if (kc < 31) {
            const int h0n = (kc + 1) * 16;
            {
                int k = tid >> 5, u = tid & 31;
                va = *(const float4*)(Qb + (size_t)(h0n + k) * Sn + q0 + 4 * u);
            }
#pragma unroll
            for (int i = 0; i < 2; i++) {
                int fl = i * 512 + tid, k = fl >> 6, u = fl & 63;
                vb[i] = *(const float4*)(Pb + (size_t)(h0n + k) * Sn + 4 * u);
            }
        }

        const uint32_t abh = sb + SCR + cur * P1_BUF;
        const uint32_t abl = abh + P1_ALO;
        const uint32_t bbh = sb + SCR + cur * P1_BUF + P1_BHI;
        const uint32_t bbl = sb + SCR + cur * P1_BUF + P1_BLO;

        uint32_t ah[2][4], al[2][4];
#pragma unroll
        for (int mf = 0; mf < 2; mf++) {
            uint32_t off = (uint32_t)(arowA * 272 + (R0 + mf * 16 + acol8) * 2);
            ldsm4t(ah[mf], abh + off);
            ldsm4t(al[mf], abl + off);
        }
#pragma unroll
        for (int nh = 0; nh < 4; nh++) {
            uint32_t off = (uint32_t)(browB * 528 + (C0 + nh * 16 + bcol8) * 2);
            uint32_t bh[4], bl[4];
            ldsm4t(bh, bbh + off);
            ldsm4t(bl, bbl + off);
#pragma unroll
            for (int mf = 0; mf < 2; mf++) {
                mma16816(acc[mf][2*nh],   ah[mf], bh[0], bh[1]);
                mma16816(acc[mf][2*nh],   ah[mf], bl[0], bl[1]);
                mma16816(acc[mf][2*nh],   al[mf], bh[0], bh[1]);
                mma16816(acc[mf][2*nh+1], ah[mf], bh[2], bh[3]);
                mma16816(acc[mf][2*nh+1], ah[mf], bl[2], bl[3]);
                mma16816(acc[mf][2*nh+1], al[mf], bh[2], bh[3]);
            }
        }

        if (kc < 31) {
            const uint32_t base = SCR + (cur ^ 1) * P1_BUF;
            {
                int k = tid >> 5, u = tid & 31;
                uint2 hi, lo; split4(va, hi, lo);
                *(uint2*)(smb + base + k * 272 + u * 8) = hi;
                *(uint2*)(smb + base + P1_ALO + k * 272 + u * 8) = lo;
            }
#pragma unroll
            for (int i = 0; i < 2; i++) {
                int fl = i * 512 + tid, k = fl >> 6, u = fl & 63;
                uint2 hi, lo; split4(vb[i], hi, lo);
                *(uint2*)(smb + base + P1_BHI + k * 528 + u * 8) = hi;
                *(uint2*)(smb + base + P1_BLO + k * 528 + u * 8) = lo;
            }
        }
        __syncthreads();
    }

    // ---------------- Softmax (registers + small smem reduce) -------------
    float pmb[8][2], qv[2][2];
#pragma unroll
    for (int nf = 0; nf < 8; nf++) {
        pmb[nf][0] = smf[PMNEG/4 + C0 + nf * 8 + 2 * c2];
        pmb[nf][1] = smf[PMNEG/4 + C0 + nf * 8 + 2 * c2 + 1];
    }
#pragma unroll
    for (int mf = 0; mf < 2; mf++) {
        qv[mf][0] = smf[QMV/4 + R0 + mf * 16 + g];
        qv[mf][1] = smf[QMV/4 + R0 + mf * 16 + g + 8];
    }
#pragma unroll
    for (int mf = 0; mf < 2; mf++)
#pragma unroll
        for (int h = 0; h < 2; h++) {
            float m = -3.4e38f;
#pragma unroll
            for (int nf = 0; nf < 8; nf++)
#pragma unroll
                for (int p = 0; p < 2; p++) {
                    float x = acc[mf][nf][2*h + p] + qv[mf][h] * pmb[nf][p];
                    acc[mf][nf][2*h + p] = x;
                    m = fmaxf(m, x);
                }
            m = fmaxf(m, __shfl_xor_sync(0xffffffffu, m, 1));
            m = fmaxf(m, __shfl_xor_sync(0xffffffffu, m, 2));
            if (c2 == 0) smf[RED1/4 + (R0 + mf * 16 + g + 8 * h) * 4 + wn] = m;
        }
    __syncthreads();
#pragma unroll
    for (int mf = 0; mf < 2; mf++)
#pragma unroll
        for (int h = 0; h < 2; h++) {
            const int row = R0 + mf * 16 + g + 8 * h;
            float m = fmaxf(fmaxf(smf[RED1/4 + row*4], smf[RED1/4 + row*4 + 1]),
                            fmaxf(smf[RED1/4 + row*4 + 2], smf[RED1/4 + row*4 + 3]));
            float s = 0.0f;
#pragma unroll
            for (int nf = 0; nf < 8; nf++)
#pragma unroll
                for (int p = 0; p < 2; p++) {
                    float e = __expf(acc[mf][nf][2*h + p] - m);
                    acc[mf][nf][2*h + p] = e;
                    s += e;
                }
            s += __shfl_xor_sync(0xffffffffu, s, 1);
            s += __shfl_xor_sync(0xffffffffu, s, 2);
            if (c2 == 0) smf[RED2/4 + row * 4 + wn] = s;
        }
    __syncthreads();
#pragma unroll
    for (int mf = 0; mf < 2; mf++)
#pragma unroll
        for (int h = 0; h < 2; h++) {
            const int row = R0 + mf * 16 + g + 8 * h;
            float s = smf[RED2/4 + row*4] + smf[RED2/4 + row*4 + 1] +
                      smf[RED2/4 + row*4 + 2] + smf[RED2/4 + row*4 + 3];
            const float inv = 1.0f / s;
#pragma unroll
            for (int nf = 0; nf < 8; nf++) {
                float v0 = acc[mf][nf][2*h]     * inv;
                float v1 = acc[mf][nf][2*h + 1] * inv;
                uint32_t hiw = pack2(v0, v1);
                uint32_t low = pack2res(v0, v1, hiw);
                uint32_t off = (uint32_t)(row * 528 + (C0 + nf * 8 + 2 * c2) * 2);
                *(uint32_t*)(smb + ATT_HI + off) = hiw;
                *(uint32_t*)(smb + ATT_LO + off) = low;
            }
        }
    __syncthreads();

    // ---------------- Phase 2: q_tilda = att @ P^T + concat ---------------
    const int C2_0 = wn * 16;            // 16 h cols per warp per tile
    const int j4 = tid & 15, fch = (tid >> 4) & 3, g2 = tid >> 6;   // g2 0..7
    const int mrow = tid & 127, qhalf = tid >> 7;                   // 0..3

    // prefetch tile 0: B2 (8 float4/thread) — n = fl>>6, u = fl&63
    float4 vb2[8];
#pragma unroll
    for (int i = 0; i < 8; i++) {
        int fl = i * 512 + tid, n = fl >> 6, u = fl & 63;
        vb2[i] = *(const float4*)(Pb + (size_t)n * Sn + 4 * u);
    }

    for (int t = 0; t < 8; ++t) {
        const int h0 = t * 64;
        // stage B2 from prefetch regs
#pragma unroll
        for (int i = 0; i < 8; i++) {
            int fl = i * 512 + tid, n = fl >> 6, u = fl & 63;
            uint2 hi, lo; split4(vb2[i], hi, lo);
            *(uint2*)(smb + SCR + n * 528 + u * 8) = hi;
            *(uint2*)(smb + SCR + B2_LO_OFF + n * 528 + u * 8) = lo;
        }
        __syncthreads();

        // issue long-latency loads: next tile's B2, this tile's Q^T
        if (t < 7) {
            const int h0n = h0 + 64;
#pragma unroll
            for (int i = 0; i < 8; i++) {
                int fl = i * 512 + tid, n = fl >> 6, u = fl & 63;
                vb2[i] = *(const float4*)(Pb + (size_t)(h0n + n) * Sn + 4 * u);
            }
        }
        float qtv[16];
#pragma unroll
        for (int j = 0; j < 16; j++) {
            const int hh = qhalf * 16 + j;
            qtv[j] = Qb[(size_t)(h0 + hh) * Sn + q0 + mrow];
        }

        float acc2[2][2][4];
#pragma unroll
        for (int a = 0; a < 2; a++)
#pragma unroll
            for (int c = 0; c < 2; c++)
#pragma unroll
                for (int j = 0; j < 4; j++) acc2[a][c][j] = 0.0f;

        for (int ks = 0; ks < 16; ++ks) {
            const int k0 = ks * 16;
            uint32_t ah2[2][4], al2[2][4];
#pragma unroll
            for (int mf = 0; mf < 2; mf++) {
                uint32_t off = (uint32_t)((R0 + mf * 16 + p2Ar) * 528 + (k0 + p2Ac8) * 2);
                ldsm4(ah2[mf], sb + ATT_HI + off);
                ldsm4(al2[mf], sb + ATT_LO + off);
            }
            uint32_t bh[4], bl[4];
            {
                uint32_t off = (uint32_t)((C2_0 + p2Br) * 528 + (k0 + p2Bc8) * 2);
                ldsm4(bh, sb + SCR + off);
                ldsm4(bl, sb + SCR + B2_LO_OFF + off);
            }
#pragma unroll
            for (int mf = 0; mf < 2; mf++) {
                mma16816(acc2[mf][0], ah2[mf], bh[0], bh[1]);
                mma16816(acc2[mf][0], ah2[mf], bl[0], bl[1]);
                mma16816(acc2[mf][0], al2[mf], bh[0], bh[1]);
                mma16816(acc2[mf][1], ah2[mf], bh[2], bh[3]);
                mma16816(acc2[mf][1], ah2[mf], bl[2], bl[3]);
                mma16816(acc2[mf][1], al2[mf], bh[2], bh[3]);
            }
        }
        __syncthreads();   // B2 consumed; SD2/SQT may overwrite

        // stage D2 + Q^T
#pragma unroll
        for (int mf = 0; mf < 2; mf++)
#pragma unroll
            for (int nf = 0; nf < 2; nf++)
#pragma unroll
                for (int h = 0; h < 2; h++) {
                    const int row = R0 + mf * 16 + g + 8 * h;
                    const int col = C2_0 + nf * 8 + 2 * c2;
                    *(float2*)(smf + SCR/4 + row * 68 + col) =
                        make_float2(acc2[mf][nf][2*h], acc2[mf][nf][2*h + 1]);
                }
#pragma unroll
        for (int j = 0; j < 16; j++) {
            const int hh = qhalf * 16 + j;
            smf[SCR/4 + SQT_OFF/4 + mrow * 68 + hh] = qtv[j];
        }
        __syncthreads();

        // concat write: [q_t, q_tilda, q_t - q_tilda, q_t * q_tilda]
#pragma unroll 4
        for (int mp = 0; mp < 16; mp++) {
            const int mm = mp * 8 + g2;
            float4 qt = *(const float4*)(smf + SCR/4 + SQT_OFF/4 + mm * 68 + j4 * 4);
            float4 td = *(const float4*)(smf + SCR/4 + mm * 68 + j4 * 4);
            float4 o;
            if      (fch == 0) o = qt;
            else if (fch == 1) o = td;
            else if (fch == 2) o = make_float4(qt.x - td.x, qt.y - td.y, qt.z - td.z, qt.w - td.w);
            else               o = make_float4(qt.x * td.x, qt.y * td.y, qt.z * td.z, qt.w * td.w);
            *(float4*)(out + ((size_t)(b * Sn + q0 + mm)) * 2048 + fch * 512 + h0 + j4 * 4) = o;
        }
        __syncthreads();
    }
}

extern "C" void kernel_launch(void* const* d_in, const int* in_sizes, int n_in,
                              void* d_out, int out_size)
{
    const float* Q  = (const float*)d_in[0];
    const float* P  = (const float*)d_in[1];
    const int*   qm = (const int*)d_in[2];
    const int*   pm = (const int*)d_in[3];
    float*       O  = (float*)d_out;

    cudaFuncSetAttribute(rml_mma_kernel,
                         cudaFuncAttributeMaxDynamicSharedMemorySize, SMEM_BYTES);

    rml_mma_kernel<<<512, 512, SMEM_BYTES>>>(Q, P, qm, pm, O);
}

// round 5
// speedup vs baseline: 2.1504x; 1.0115x over previous
#include <cuda_runtime.h>
#include <cuda_bf16.h>
#include <cstdint>

#define NEG_INF_F (-1000000.0f)

constexpr int Hh = 512, Sn = 256;           // H, Sq=Sp
constexpr int TQ = 64;                      // q rows per CTA

// ---- smem byte offsets ----
constexpr int ATT_HI = 0;                   // [64 m][256 k] bf16, row stride 528
constexpr int ATT_LO = 33792;
constexpr int SCR    = 67584;               // 43008-byte aliased scratch
//   phase1 (double buffered, 21504/buf): A_hi(16x144) A_lo B_hi(16x528) B_lo
constexpr int P1_ALO = 2304, P1_BHI = 4608, P1_BLO = 13056, P1_BUF = 21504;
//   phase2: B2 chunk [64n][128k] stride 272 -> 17408 per half
constexpr int B2_LO_OFF = 17408;
//   epilogue: SD2 float[64][68]=17408, SQT
constexpr int SQT_OFF = 17408;
constexpr int PMNEG = 110592;               // float[256]
constexpr int QMV   = 111616;               // float[64]
constexpr int RED1  = 111872;               // float[64][4]
constexpr int RED2  = 112896;               // float[64][4]
constexpr int SMEM_BYTES = 113920;

__device__ __forceinline__ uint32_t smem_u32(const void* p) {
    uint32_t a;
    asm("{ .reg .u64 t; cvta.to.shared.u64 t, %1; cvt.u32.u64 %0, t; }" : "=r"(a) : "l"(p));
    return a;
}
__device__ __forceinline__ void ldsm4(uint32_t a[4], uint32_t addr) {
    asm volatile("ldmatrix.sync.aligned.m8n8.x4.shared.b16 {%0,%1,%2,%3}, [%4];"
                 : "=r"(a[0]), "=r"(a[1]), "=r"(a[2]), "=r"(a[3]) : "r"(addr));
}
__device__ __forceinline__ void ldsm4t(uint32_t a[4], uint32_t addr) {
    asm volatile("ldmatrix.sync.aligned.m8n8.x4.trans.shared.b16 {%0,%1,%2,%3}, [%4];"
                 : "=r"(a[0]), "=r"(a[1]), "=r"(a[2]), "=r"(a[3]) : "r"(addr));
}
__device__ __forceinline__ void mma16816(float d[4], const uint32_t a[4],
                                         uint32_t b0, uint32_t b1) {
    asm volatile("mma.sync.aligned.m16n8k16.row.col.f32.bf16.bf16.f32 "
                 "{%0,%1,%2,%3}, {%4,%5,%6,%7}, {%8,%9}, {%0,%1,%2,%3};"
                 : "+f"(d[0]), "+f"(d[1]), "+f"(d[2]), "+f"(d[3])
                 : "r"(a[0]), "r"(a[1]), "r"(a[2]), "r"(a[3]), "r"(b0), "r"(b1));
}
__device__ __forceinline__ void split4(float4 v, uint2& hi, uint2& lo) {
    __nv_bfloat162 h01 = __float22bfloat162_rn(make_float2(v.x, v.y));
    __nv_bfloat162 h23 = __float22bfloat162_rn(make_float2(v.z, v.w));
    float2 f01 = __bfloat1622float2(h01), f23 = __bfloat1622float2(h23);
    __nv_bfloat162 l01 = __float22bfloat162_rn(make_float2(v.x - f01.x, v.y - f01.y));
    __nv_bfloat162 l23 = __float22bfloat162_rn(make_float2(v.z - f23.x, v.w - f23.y));
    hi.x = *reinterpret_cast<uint32_t*>(&h01); hi.y = *reinterpret_cast<uint32_t*>(&h23);
    lo.x = *reinterpret_cast<uint32_t*>(&l01); lo.y = *reinterpret_cast<uint32_t*>(&l23);
}
__device__ __forceinline__ uint32_t pack2(float v0, float v1) {
    __nv_bfloat162 h = __float22bfloat162_rn(make_float2(v0, v1));
    return *reinterpret_cast<uint32_t*>(&h);
}
__device__ __forceinline__ uint32_t pack2res(float v0, float v1, uint32_t hiw) {
    __nv_bfloat162 h = *reinterpret_cast<__nv_bfloat162*>(&hiw);
    float2 f = __bfloat1622float2(h);
    __nv_bfloat162 l = __float22bfloat162_rn(make_float2(v0 - f.x, v1 - f.y));
    return *reinterpret_cast<uint32_t*>(&l);
}

__global__ void __launch_bounds__(256, 2)
rml_mma_kernel(const float* __restrict__ Q, const float* __restrict__ P,
               const int* __restrict__ qmask, const int* __restrict__ pmask,
               float* __restrict__ out)
{
    extern __shared__ char smb[];
    const uint32_t sb = smem_u32(smb);
    float* smf = reinterpret_cast<float*>(smb);

    const int tid = threadIdx.x, lane = tid & 31, wid = tid >> 5;
    const int g = lane >> 2, c2 = lane & 3, sel = lane >> 3, r8 = lane & 7;
    const int wm = wid >> 2, wn = wid & 3;
    const int R0 = wm * 32, C0 = wn * 64;           // phase1 warp tile 32m x 64n
    const int b = blockIdx.x >> 2, q0 = (blockIdx.x & 3) * TQ;

    const float* Qb = Q + (size_t)b * Hh * Sn;
    const float* Pb = P + (size_t)b * Hh * Sn;

    smf[PMNEG/4 + tid] = pmask[b * Sn + tid] ? NEG_INF_F : 0.0f;
    if (tid < 64) smf[QMV/4 + tid] = qmask[b * Sn + q0 + tid] ? 1.0f : 0.0f;

    // lane-constant ldmatrix offsets
    const int arowA = (sel >> 1) * 8 + r8, acol8 = (sel & 1) * 8;   // phase1 A (trans, [k][m])
    const int browB = (sel & 1) * 8 + r8, bcol8 = (sel >> 1) * 8;   // phase1 B (trans, [k][n])
    const int p2Ar  = (sel & 1) * 8 + r8, p2Ac8 = (sel >> 1) * 8;   // phase2 A ([m][k])
    const int p2Br  = (sel >> 1) * 8 + r8, p2Bc8 = (sel & 1) * 8;   // phase2 B ([n][k])

    float acc[2][8][4];
#pragma unroll
    for (int a = 0; a < 2; a++)
#pragma unroll
        for (int c = 0; c < 8; c++)
#pragma unroll
            for (int j = 0; j < 4; j++) acc[a][c][j] = 0.0f;

    // ---------------- Phase 1: sim = Q^T @ P (regs) -----------------------
    // stage chunk 0 (256 threads: 1 float4 Q, 4 float4 P each)
    {
        int k = tid >> 4, u = tid & 15;
        float4 v = *(const float4*)(Qb + (size_t)k * Sn + q0 + 4 * u);
        uint2 hi, lo; split4(v, hi, lo);
        *(uint2*)(smb + SCR + k * 144 + u * 8) = hi;
        *(uint2*)(smb + SCR + P1_ALO + k * 144 + u * 8) = lo;
#pragma unroll
        for (int i = 0; i < 4; i++) {
            int fl = i * 256 + tid, kk = fl >> 6, uu = fl & 63;
            float4 w = *(const float4*)(Pb + (size_t)kk * Sn + 4 * uu);
            uint2 h2, l2; split4(w, h2, l2);
            *(uint2*)(smb + SCR + P1_BHI + kk * 528 + uu * 8) = h2;
            *(uint2*)(smb + SCR + P1_BLO + kk * 528 + uu * 8) = l2;
        }
    }
    __syncthreads();

    for (int kc = 0; kc < 32; ++kc) {
        const int cur = kc & 1;
        // prefetch next chunk into regs
        float4 va, vb[4];
        if (kc < 31) {
            const int h0n = (kc + 1) * 16;
            {
                int k = tid >> 4, u = tid & 15;
                va = *(const float4*)(Qb + (size_t)(h0n + k) * Sn + q0 + 4 * u);
            }
#pragma unroll
            for (int i = 0; i < 4; i++) {
                int fl = i * 256 + tid, k = fl >> 6, u = fl & 63;
                vb[i] = *(const float4*)(Pb + (size_t)(h0n + k) * Sn + 4 * u);
            }
        }

        const uint32_t abh = sb + SCR + cur * P1_BUF;
        const uint32_t abl = abh + P1_ALO;
        const uint32_t bbh = sb + SCR + cur * P1_BUF + P1_BHI;
        const uint32_t bbl = sb + SCR + cur * P1_BUF + P1_BLO;

        uint32_t ah[2][4], al[2][4];
#pragma unroll
        for (int mf = 0; mf < 2; mf++) {
            uint32_t off = (uint32_t)(arowA * 144 + (R0 + mf * 16 + acol8) * 2);
            ldsm4t(ah[mf], abh + off);
            ldsm4t(al[mf], abl + off);
        }
#pragma unroll
        for (int nh = 0; nh < 4; nh++) {
            uint32_t off = (uint32_t)(browB * 528 + (C0 + nh * 16 + bcol8) * 2);
            uint32_t bh[4], bl[4];
            ldsm4t(bh, bbh + off);
            ldsm4t(bl, bbl + off);
#pragma unroll
            for (int mf = 0; mf < 2; mf++) {
                mma16816(acc[mf][2*nh],   ah[mf], bh[0], bh[1]);
                mma16816(acc[mf][2*nh],   ah[mf], bl[0], bl[1]);
                mma16816(acc[mf][2*nh],   al[mf], bh[0], bh[1]);
                mma16816(acc[mf][2*nh+1], ah[mf], bh[2], bh[3]);
                mma16816(acc[mf][2*nh+1], ah[mf], bl[2], bl[3]);
                mma16816(acc[mf][2*nh+1], al[mf], bh[2], bh[3]);
            }
        }

        if (kc < 31) {
            const uint32_t base = SCR + (cur ^ 1) * P1_BUF;
            {
                int k = tid >> 4, u = tid & 15;
                uint2 hi, lo; split4(va, hi, lo);
                *(uint2*)(smb + base + k * 144 + u * 8) = hi;
                *(uint2*)(smb + base + P1_ALO + k * 144 + u * 8) = lo;
            }
#pragma unroll
            for (int i = 0; i < 4; i++) {
                int fl = i * 256 + tid, k = fl >> 6, u = fl & 63;
                uint2 hi, lo; split4(vb[i], hi, lo);
                *(uint2*)(smb + base + P1_BHI + k * 528 + u * 8) = hi;
                *(uint2*)(smb + base + P1_BLO + k * 528 + u * 8) = lo;
            }
        }
        __syncthreads();
    }

    // ---------------- Softmax (registers + small smem reduce) -------------
    float pmb[8][2], qv[2][2];
#pragma unroll
    for (int nf = 0; nf < 8; nf++) {
        pmb[nf][0] = smf[PMNEG/4 + C0 + nf * 8 + 2 * c2];
        pmb[nf][1] = smf[PMNEG/4 + C0 + nf * 8 + 2 * c2 + 1];
    }
#pragma unroll
    for (int mf = 0; mf < 2; mf++) {
        qv[mf][0] = smf[QMV/4 + R0 + mf * 16 + g];
        qv[mf][1] = smf[QMV/4 + R0 + mf * 16 + g + 8];
    }
#pragma unroll
    for (int mf = 0; mf < 2; mf++)
#pragma unroll
        for (int h = 0; h < 2; h++) {
            float m = -3.4e38f;
#pragma unroll
            for (int nf = 0; nf < 8; nf++)
#pragma unroll
                for (int p = 0; p < 2; p++) {
                    float x = acc[mf][nf][2*h + p] + qv[mf][h] * pmb[nf][p];
                    acc[mf][nf][2*h + p] = x;
                    m = fmaxf(m, x);
                }
            m = fmaxf(m, __shfl_xor_sync(0xffffffffu, m, 1));
            m = fmaxf(m, __shfl_xor_sync(0xffffffffu, m, 2));
            if (c2 == 0) smf[RED1/4 + (R0 + mf * 16 + g + 8 * h) * 4 + wn] = m;
        }
    __syncthreads();
#pragma unroll
    for (int mf = 0; mf < 2; mf++)
#pragma unroll
        for (int h = 0; h < 2; h++) {
            const int row = R0 + mf * 16 + g + 8 * h;
            float m = fmaxf(fmaxf(smf[RED1/4 + row*4], smf[RED1/4 + row*4 + 1]),
                            fmaxf(smf[RED1/4 + row*4 + 2], smf[RED1/4 + row*4 + 3]));
            float s = 0.0f;
#pragma unroll
            for (int nf = 0; nf < 8; nf++)
#pragma unroll
                for (int p = 0; p < 2; p++) {
                    float e = __expf(acc[mf][nf][2*h + p] - m);
                    acc[mf][nf][2*h + p] = e;
                    s += e;
                }
            s += __shfl_xor_sync(0xffffffffu, s, 1);
            s += __shfl_xor_sync(0xffffffffu, s, 2);
            if (c2 == 0) smf[RED2/4 + row * 4 + wn] = s;
        }
    __syncthreads();
#pragma unroll
    for (int mf = 0; mf < 2; mf++)
#pragma unroll
        for (int h = 0; h < 2; h++) {
            const int row = R0 + mf * 16 + g + 8 * h;
            float s = smf[RED2/4 + row*4] + smf[RED2/4 + row*4 + 1] +
                      smf[RED2/4 + row*4 + 2] + smf[RED2/4 + row*4 + 3];
            const float inv = 1.0f / s;
#pragma unroll
            for (int nf = 0; nf < 8; nf++) {
                float v0 = acc[mf][nf][2*h]     * inv;
                float v1 = acc[mf][nf][2*h + 1] * inv;
                uint32_t hiw = pack2(v0, v1);
                uint32_t low = pack2res(v0, v1, hiw);
                uint32_t off = (uint32_t)(row * 528 + (C0 + nf * 8 + 2 * c2) * 2);
                *(uint32_t*)(smb + ATT_HI + off) = hiw;
                *(uint32_t*)(smb + ATT_LO + off) = low;
            }
        }

    // ---------------- Phase 2: q_tilda = att @ P^T + concat ---------------
    const int C2_0 = wn * 16;            // 16 h cols per warp per tile
    const int j4 = tid & 15, fch = (tid >> 4) & 3, g2 = tid >> 6;   // g2 0..3
    const int mrow = tid & 63, qhalf = tid >> 6;                    // 0..3

    // prefetch tile0/chunk0: B2 [64n][128k] (8 float4/thread)
    float4 vb2[8];
#pragma unroll
    for (int i = 0; i < 8; i++) {
        int fl = i * 256 + tid, n = fl >> 5, u = fl & 31;
        vb2[i] = *(const float4*)(Pb + (size_t)n * Sn + 4 * u);
    }

    for (int t = 0; t < 8; ++t) {
        const int h0 = t * 64;
        float acc2[2][2][4];
#pragma unroll
        for (int a = 0; a < 2; a++)
#pragma unroll
            for (int c = 0; c < 2; c++)
#pragma unroll
                for (int j = 0; j < 4; j++) acc2[a][c][j] = 0.0f;

        float qtv[16];

#pragma unroll 1
        for (int cch = 0; cch < 2; ++cch) {
            __syncthreads();   // scratch free (prior readers done)
            // stage current B2 chunk from prefetch regs
#pragma unroll
            for (int i = 0; i < 8; i++) {
                int fl = i * 256 + tid, n = fl >> 5, u = fl & 31;
                uint2 hi, lo; split4(vb2[i], hi, lo);
                *(uint2*)(smb + SCR + n * 272 + u * 8) = hi;
                *(uint2*)(smb + SCR + B2_LO_OFF + n * 272 + u * 8) = lo;
            }
            // prefetch next chunk: (t, k=128) or (t+1, k=0)
            if (cch == 0 || t < 7) {
                const int h0n = (cch == 0) ? h0 : h0 + 64;
                const int k0n = (cch == 0) ? 128 : 0;
#pragma unroll
                for (int i = 0; i < 8; i++) {
                    int fl = i * 256 + tid, n = fl >> 5, u = fl & 31;
                    vb2[i] = *(const float4*)(Pb + (size_t)(h0n + n) * Sn + k0n + 4 * u);
                }
            }
            if (cch == 0) {   // overlap Q^T loads with both chunks' MMAs
#pragma unroll
                for (int j = 0; j < 16; j++)
                    qtv[j] = Qb[(size_t)(h0 + qhalf * 16 + j) * Sn + q0 + mrow];
            }
            __syncthreads();

            const int kg = cch * 128;
#pragma unroll 2
            for (int ks = 0; ks < 8; ++ks) {
                const int k0 = ks * 16;
                uint32_t ah2[2][4], al2[2][4];
#pragma unroll
                for (int mf = 0; mf < 2; mf++) {
                    uint32_t off = (uint32_t)((R0 + mf * 16 + p2Ar) * 528 + (kg + k0 + p2Ac8) * 2);
                    ldsm4(ah2[mf], sb + ATT_HI + off);
                    ldsm4(al2[mf], sb + ATT_LO + off);
                }
                uint32_t bh[4], bl[4];
                {
                    uint32_t off = (uint32_t)((C2_0 + p2Br) * 272 + (k0 + p2Bc8) * 2);
                    ldsm4(bh, sb + SCR + off);
                    ldsm4(bl, sb + SCR + B2_LO_OFF + off);
                }
#pragma unroll
                for (int mf = 0; mf < 2; mf++) {
                    mma16816(acc2[mf][0], ah2[mf], bh[0], bh[1]);
                    mma16816(acc2[mf][0], ah2[mf], bl[0], bl[1]);
                    mma16816(acc2[mf][0], al2[mf], bh[0], bh[1]);
                    mma16816(acc2[mf][1], ah2[mf], bh[2], bh[3]);
                    mma16816(acc2[mf][1], ah2[mf], bl[2], bl[3]);
                    mma16816(acc2[mf][1], al2[mf], bh[2], bh[3]);
                }
            }
        }
        __syncthreads();   // B2 consumed; SD2/SQT may overwrite

        // stage D2 + Q^T
#pragma unroll
        for (int mf = 0; mf < 2; mf++)
#pragma unroll
            for (int nf = 0; nf < 2; nf++)
#pragma unroll
                for (int h = 0; h < 2; h++) {
                    const int row = R0 + mf * 16 + g + 8 * h;
                    const int col = C2_0 + nf * 8 + 2 * c2;
                    *(float2*)(smf + SCR/4 + row * 68 + col) =
                        make_float2(acc2[mf][nf][2*h], acc2[mf][nf][2*h + 1]);
                }
#pragma unroll
        for (int j = 0; j < 16; j++)
            smf[SCR/4 + SQT_OFF/4 + mrow * 68 + qhalf * 16 + j] = qtv[j];
        __syncthreads();

        // concat write: [q_t, q_tilda, q_t - q_tilda, q_t * q_tilda]
#pragma unroll 4
        for (int mp = 0; mp < 16; mp++) {
            const int mm = mp * 4 + g2;
            float4 qt = *(const float4*)(smf + SCR/4 + SQT_OFF/4 + mm * 68 + j4 * 4);
            float4 td = *(const float4*)(smf + SCR/4 + mm * 68 + j4 * 4);
            float4 o;
            if      (fch == 0) o = qt;
            else if (fch == 1) o = td;
            else if (fch == 2) o = make_float4(qt.x - td.x, qt.y - td.y, qt.z - td.z, qt.w - td.w);
            else               o = make_float4(qt.x * td.x, qt.y * td.y, qt.z * td.z, qt.w * td.w);
            *(float4*)(out + ((size_t)(b * Sn + q0 + mm)) * 2048 + fch * 512 + h0 + j4 * 4) = o;
        }
    }
}

extern "C" void kernel_launch(void* const* d_in, const int* in_sizes, int n_in,
                              void* d_out, int out_size)
{
    const float* Q  = (const float*)d_in[0];
    const float* P  = (const float*)d_in[1];
    const int*   qm = (const int*)d_in[2];
    const int*   pm = (const int*)d_in[3];
    float*       O  = (float*)d_out;

    cudaFuncSetAttribute(rml_mma_kernel,
                         cudaFuncAttributeMaxDynamicSharedMemorySize, SMEM_BYTES);

    rml_mma_kernel<<<1024, 256, SMEM_BYTES>>>(Q, P, qm, pm, O);
}

// round 6
// speedup vs baseline: 2.6439x; 1.2295x over previous
#include <cuda_runtime.h>
#include <cuda_bf16.h>
#include <cuda_fp16.h>
#include <cstdint>

#define NEG_INF_F (-1000000.0f)

constexpr int Hh = 512, Sn = 256;           // H, Sq=Sp
constexpr int TQ = 64;                      // q rows per CTA

// ---- smem byte offsets ----
constexpr int ATT = 0;                      // [64 m][256 k] fp16, row stride 528 = 33792 B
constexpr int SCR = 33792;                  // 43008-byte aliased scratch
//   phase1 (double buffered, 21504/buf): A_hi(16x144) A_lo B_hi(16x528) B_lo
constexpr int P1_ALO = 2304, P1_BHI = 4608, P1_BLO = 13056, P1_BUF = 21504;
//   phase2: B2 chunk [64n][128k] fp16 stride 272 -> 17408 per half (hi, lo)
constexpr int B2_LO_OFF = 17408;
//   epilogue: SD2 float[64][68]=17408, SQT
constexpr int SQT_OFF = 17408;
constexpr int PMNEG = 76800;                // float[256]
constexpr int QMV   = 77824;                // float[64]
constexpr int RED1  = 78080;                // float[64][4]
constexpr int RED2  = 79104;                // float[64][4]
constexpr int SMEM_BYTES = 80128;

__device__ __forceinline__ uint32_t smem_u32(const void* p) {
    uint32_t a;
    asm("{ .reg .u64 t; cvta.to.shared.u64 t, %1; cvt.u32.u64 %0, t; }" : "=r"(a) : "l"(p));
    return a;
}
__device__ __forceinline__ void ldsm4(uint32_t a[4], uint32_t addr) {
    asm volatile("ldmatrix.sync.aligned.m8n8.x4.shared.b16 {%0,%1,%2,%3}, [%4];"
                 : "=r"(a[0]), "=r"(a[1]), "=r"(a[2]), "=r"(a[3]) : "r"(addr));
}
__device__ __forceinline__ void ldsm4t(uint32_t a[4], uint32_t addr) {
    asm volatile("ldmatrix.sync.aligned.m8n8.x4.trans.shared.b16 {%0,%1,%2,%3}, [%4];"
                 : "=r"(a[0]), "=r"(a[1]), "=r"(a[2]), "=r"(a[3]) : "r"(addr));
}
__device__ __forceinline__ void mma16816(float d[4], const uint32_t a[4],
                                         uint32_t b0, uint32_t b1) {
    asm volatile("mma.sync.aligned.m16n8k16.row.col.f32.bf16.bf16.f32 "
                 "{%0,%1,%2,%3}, {%4,%5,%6,%7}, {%8,%9}, {%0,%1,%2,%3};"
                 : "+f"(d[0]), "+f"(d[1]), "+f"(d[2]), "+f"(d[3])
                 : "r"(a[0]), "r"(a[1]), "r"(a[2]), "r"(a[3]), "r"(b0), "r"(b1));
}
__device__ __forceinline__ void mma16816h(float d[4], const uint32_t a[4],
                                          uint32_t b0, uint32_t b1) {
    asm volatile("mma.sync.aligned.m16n8k16.row.col.f32.f16.f16.f32 "
                 "{%0,%1,%2,%3}, {%4,%5,%6,%7}, {%8,%9}, {%0,%1,%2,%3};"
                 : "+f"(d[0]), "+f"(d[1]), "+f"(d[2]), "+f"(d[3])
                 : "r"(a[0]), "r"(a[1]), "r"(a[2]), "r"(a[3]), "r"(b0), "r"(b1));
}
// bf16 2-way split of 4 floats (phase 1)
__device__ __forceinline__ void split4(float4 v, uint2& hi, uint2& lo) {
    __nv_bfloat162 h01 = __float22bfloat162_rn(make_float2(v.x, v.y));
    __nv_bfloat162 h23 = __float22bfloat162_rn(make_float2(v.z, v.w));
    float2 f01 = __bfloat1622float2(h01), f23 = __bfloat1622float2(h23);
    __nv_bfloat162 l01 = __float22bfloat162_rn(make_float2(v.x - f01.x, v.y - f01.y));
    __nv_bfloat162 l23 = __float22bfloat162_rn(make_float2(v.z - f23.x, v.w - f23.y));
    hi.x = *reinterpret_cast<uint32_t*>(&h01); hi.y = *reinterpret_cast<uint32_t*>(&h23);
    lo.x = *reinterpret_cast<uint32_t*>(&l01); lo.y = *reinterpret_cast<uint32_t*>(&l23);
}
// fp16 2-way split of 4 floats (phase 2 B)
__device__ __forceinline__ void split4h(float4 v, uint2& hi, uint2& lo) {
    __half2 h01 = __float22half2_rn(make_float2(v.x, v.y));
    __half2 h23 = __float22half2_rn(make_float2(v.z, v.w));
    float2 f01 = __half22float2(h01), f23 = __half22float2(h23);
    __half2 l01 = __float22half2_rn(make_float2(v.x - f01.x, v.y - f01.y));
    __half2 l23 = __float22half2_rn(make_float2(v.z - f23.x, v.w - f23.y));
    hi.x = *reinterpret_cast<uint32_t*>(&h01); hi.y = *reinterpret_cast<uint32_t*>(&h23);
    lo.x = *reinterpret_cast<uint32_t*>(&l01); lo.y = *reinterpret_cast<uint32_t*>(&l23);
}
__device__ __forceinline__ uint32_t pack2h(float v0, float v1) {
    __half2 h = __float22half2_rn(make_float2(v0, v1));
    return *reinterpret_cast<uint32_t*>(&h);
}

__global__ void __launch_bounds__(256, 2)
rml_mma_kernel(const float* __restrict__ Q, const float* __restrict__ P,
               const int* __restrict__ qmask, const int* __restrict__ pmask,
               float* __restrict__ out)
{
    extern __shared__ char smb[];
    const uint32_t sb = smem_u32(smb);
    float* smf = reinterpret_cast<float*>(smb);

    const int tid = threadIdx.x, lane = tid & 31, wid = tid >> 5;
    const int g = lane >> 2, c2 = lane & 3, sel = lane >> 3, r8 = lane & 7;
    const int wm = wid >> 2, wn = wid & 3;
    const int R0 = wm * 32, C0 = wn * 64;           // phase1 warp tile 32m x 64n
    const int b = blockIdx.x >> 2, q0 = (blockIdx.x & 3) * TQ;

    const float* Qb = Q + (size_t)b * Hh * Sn;
    const float* Pb = P + (size_t)b * Hh * Sn;

    smf[PMNEG/4 + tid] = pmask[b * Sn + tid] ? NEG_INF_F : 0.0f;
    if (tid < 64) smf[QMV/4 + tid] = qmask[b * Sn + q0 + tid] ? 1.0f : 0.0f;

    // lane-constant ldmatrix offsets
    const int arowA = (sel >> 1) * 8 + r8, acol8 = (sel & 1) * 8;   // phase1 A (trans, [k][m])
    const int browB = (sel & 1) * 8 + r8, bcol8 = (sel >> 1) * 8;   // phase1 B (trans, [k][n])
    const int p2Ar  = (sel & 1) * 8 + r8, p2Ac8 = (sel >> 1) * 8;   // phase2 A ([m][k])
    const int p2Br  = (sel >> 1) * 8 + r8, p2Bc8 = (sel & 1) * 8;   // phase2 B ([n][k])

    float acc[2][8][4];
#pragma unroll
    for (int a = 0; a < 2; a++)
#pragma unroll
        for (int c = 0; c < 8; c++)
#pragma unroll
            for (int j = 0; j < 4; j++) acc[a][c][j] = 0.0f;

    // ---------------- Phase 1: sim = Q^T @ P (regs, bf16 3-term) ----------
    {
        int k = tid >> 4, u = tid & 15;
        float4 v = *(const float4*)(Qb + (size_t)k * Sn + q0 + 4 * u);
        uint2 hi, lo; split4(v, hi, lo);
        *(uint2*)(smb + SCR + k * 144 + u * 8) = hi;
        *(uint2*)(smb + SCR + P1_ALO + k * 144 + u * 8) = lo;
#pragma unroll
        for (int i = 0; i < 4; i++) {
            int fl = i * 256 + tid, kk = fl >> 6, uu = fl & 63;
            float4 w = *(const float4*)(Pb + (size_t)kk * Sn + 4 * uu);
            uint2 h2, l2; split4(w, h2, l2);
            *(uint2*)(smb + SCR + P1_BHI + kk * 528 + uu * 8) = h2;
            *(uint2*)(smb + SCR + P1_BLO + kk * 528 + uu * 8) = l2;
        }
    }
    __syncthreads();

    for (int kc = 0; kc < 32; ++kc) {
        const int cur = kc & 1;
        float4 va, vb[4];
        if (kc < 31) {
            const int h0n = (kc + 1) * 16;
            {
                int k = tid >> 4, u = tid & 15;
                va = *(const float4*)(Qb + (size_t)(h0n + k) * Sn + q0 + 4 * u);
            }
#pragma unroll
            for (int i = 0; i < 4; i++) {
                int fl = i * 256 + tid, k = fl >> 6, u = fl & 63;
                vb[i] = *(const float4*)(Pb + (size_t)(h0n + k) * Sn + 4 * u);
            }
        }

        const uint32_t abh = sb + SCR + cur * P1_BUF;
        const uint32_t abl = abh + P1_ALO;
        const uint32_t bbh = sb + SCR + cur * P1_BUF + P1_BHI;
        const uint32_t bbl = sb + SCR + cur * P1_BUF + P1_BLO;

        uint32_t ah[2][4], al[2][4];
#pragma unroll
        for (int mf = 0; mf < 2; mf++) {
            uint32_t off = (uint32_t)(arowA * 144 + (R0 + mf * 16 + acol8) * 2);
            ldsm4t(ah[mf], abh + off);
            ldsm4t(al[mf], abl + off);
        }
#pragma unroll
        for (int nh = 0; nh < 4; nh++) {
            uint32_t off = (uint32_t)(browB * 528 + (C0 + nh * 16 + bcol8) * 2);
            uint32_t bh[4], bl[4];
            ldsm4t(bh, bbh + off);
            ldsm4t(bl, bbl + off);
#pragma unroll
            for (int mf = 0; mf < 2; mf++) {
                mma16816(acc[mf][2*nh],   ah[mf], bh[0], bh[1]);
                mma16816(acc[mf][2*nh],   ah[mf], bl[0], bl[1]);
                mma16816(acc[mf][2*nh],   al[mf], bh[0], bh[1]);
                mma16816(acc[mf][2*nh+1], ah[mf], bh[2], bh[3]);
                mma16816(acc[mf][2*nh+1], ah[mf], bl[2], bl[3]);
                mma16816(acc[mf][2*nh+1], al[mf], bh[2], bh[3]);
            }
        }

        if (kc < 31) {
            const uint32_t base = SCR + (cur ^ 1) * P1_BUF;
            {
                int k = tid >> 4, u = tid & 15;
                uint2 hi, lo; split4(va, hi, lo);
                *(uint2*)(smb + base + k * 144 + u * 8) = hi;
                *(uint2*)(smb + base + P1_ALO + k * 144 + u * 8) = lo;
            }
#pragma unroll
            for (int i = 0; i < 4; i++) {
                int fl = i * 256 + tid, k = fl >> 6, u = fl & 63;
                uint2 hi, lo; split4(vb[i], hi, lo);
                *(uint2*)(smb + base + P1_BHI + k * 528 + u * 8) = hi;
                *(uint2*)(smb + base + P1_BLO + k * 528 + u * 8) = lo;
            }
        }
        __syncthreads();
    }

    // ---------------- Softmax (registers + small smem reduce) -------------
    float pmb[8][2], qv[2][2];
#pragma unroll
    for (int nf = 0; nf < 8; nf++) {
        pmb[nf][0] = smf[PMNEG/4 + C0 + nf * 8 + 2 * c2];
        pmb[nf][1] = smf[PMNEG/4 + C0 + nf * 8 + 2 * c2 + 1];
    }
#pragma unroll
    for (int mf = 0; mf < 2; mf++) {
        qv[mf][0] = smf[QMV/4 + R0 + mf * 16 + g];
        qv[mf][1] = smf[QMV/4 + R0 + mf * 16 + g + 8];
    }
#pragma unroll
    for (int mf = 0; mf < 2; mf++)
#pragma unroll
        for (int h = 0; h < 2; h++) {
            float m = -3.4e38f;
#pragma unroll
            for (int nf = 0; nf < 8; nf++)
#pragma unroll
                for (int p = 0; p < 2; p++) {
                    float x = acc[mf][nf][2*h + p] + qv[mf][h] * pmb[nf][p];
                    acc[mf][nf][2*h + p] = x;
                    m = fmaxf(m, x);
                }
            m = fmaxf(m, __shfl_xor_sync(0xffffffffu, m, 1));
            m = fmaxf(m, __shfl_xor_sync(0xffffffffu, m, 2));
            if (c2 == 0) smf[RED1/4 + (R0 + mf * 16 + g + 8 * h) * 4 + wn] = m;
        }
    __syncthreads();
#pragma unroll
    for (int mf = 0; mf < 2; mf++)
#pragma unroll
        for (int h = 0; h < 2; h++) {
            const int row = R0 + mf * 16 + g + 8 * h;
            float m = fmaxf(fmaxf(smf[RED1/4 + row*4], smf[RED1/4 + row*4 + 1]),
                            fmaxf(smf[RED1/4 + row*4 + 2], smf[RED1/4 + row*4 + 3]));
            float s = 0.0f;
#pragma unroll
            for (int nf = 0; nf < 8; nf++)
#pragma unroll
                for (int p = 0; p < 2; p++) {
                    float e = __expf(acc[mf][nf][2*h + p] - m);
                    acc[mf][nf][2*h + p] = e;
                    s += e;
                }
            s += __shfl_xor_sync(0xffffffffu, s, 1);
            s += __shfl_xor_sync(0xffffffffu, s, 2);
            if (c2 == 0) smf[RED2/4 + row * 4 + wn] = s;
        }
    __syncthreads();
#pragma unroll
    for (int mf = 0; mf < 2; mf++)
#pragma unroll
        for (int h = 0; h < 2; h++) {
            const int row = R0 + mf * 16 + g + 8 * h;
            float s = smf[RED2/4 + row*4] + smf[RED2/4 + row*4 + 1] +
                      smf[RED2/4 + row*4 + 2] + smf[RED2/4 + row*4 + 3];
            const float inv = 1.0f / s;
#pragma unroll
            for (int nf = 0; nf < 8; nf++) {
                float v0 = acc[mf][nf][2*h]     * inv;
                float v1 = acc[mf][nf][2*h + 1] * inv;
                uint32_t off = (uint32_t)(row * 528 + (C0 + nf * 8 + 2 * c2) * 2);
                *(uint32_t*)(smb + ATT + off) = pack2h(v0, v1);   // fp16 attention
            }
        }

    // ---------------- Phase 2: q_tilda = att @ P^T (fp16, 2-term) ---------
    const int C2_0 = wn * 16;            // 16 h cols per warp per tile
    const int j4 = tid & 15, fch = (tid >> 4) & 3, g2 = tid >> 6;   // g2 0..3
    const int mrow = tid & 63, qhalf = tid >> 6;                    // 0..3

    // prefetch tile0/chunk0: B2 [64n][128k] (8 float4/thread)
    float4 vb2[8];
#pragma unroll
    for (int i = 0; i < 8; i++) {
        int fl = i * 256 + tid, n = fl >> 5, u = fl & 31;
        vb2[i] = *(const float4*)(Pb + (size_t)n * Sn + 4 * u);
    }

    for (int t = 0; t < 8; ++t) {
        const int h0 = t * 64;
        float acc2[2][2][4];
#pragma unroll
        for (int a = 0; a < 2; a++)
#pragma unroll
            for (int c = 0; c < 2; c++)
#pragma unroll
                for (int j = 0; j < 4; j++) acc2[a][c][j] = 0.0f;

        float qtv[16];

#pragma unroll 1
        for (int cch = 0; cch < 2; ++cch) {
            __syncthreads();   // scratch free (prior readers done)
            // stage current B2 chunk from prefetch regs (fp16 hi/lo)
#pragma unroll
            for (int i = 0; i < 8; i++) {
                int fl = i * 256 + tid, n = fl >> 5, u = fl & 31;
                uint2 hi, lo; split4h(vb2[i], hi, lo);
                *(uint2*)(smb + SCR + n * 272 + u * 8) = hi;
                *(uint2*)(smb + SCR + B2_LO_OFF + n * 272 + u * 8) = lo;
            }
            // prefetch next chunk: (t, k=128) or (t+1, k=0)
            if (cch == 0 || t < 7) {
                const int h0n = (cch == 0) ? h0 : h0 + 64;
                const int k0n = (cch == 0) ? 128 : 0;
#pragma unroll
                for (int i = 0; i < 8; i++) {
                    int fl = i * 256 + tid, n = fl >> 5, u = fl & 31;
                    vb2[i] = *(const float4*)(Pb + (size_t)(h0n + n) * Sn + k0n + 4 * u);
                }
            }
            if (cch == 0) {   // overlap Q^T loads with both chunks' MMAs
#pragma unroll
                for (int j = 0; j < 16; j++)
                    qtv[j] = Qb[(size_t)(h0 + qhalf * 16 + j) * Sn + q0 + mrow];
            }
            __syncthreads();

            const int kg = cch * 128;
#pragma unroll 2
            for (int ks = 0; ks < 8; ++ks) {
                const int k0 = ks * 16;
                uint32_t ah2[2][4];
#pragma unroll
                for (int mf = 0; mf < 2; mf++) {
                    uint32_t off = (uint32_t)((R0 + mf * 16 + p2Ar) * 528 + (kg + k0 + p2Ac8) * 2);
                    ldsm4(ah2[mf], sb + ATT + off);
                }
                uint32_t bh[4], bl[4];
                {
                    uint32_t off = (uint32_t)((C2_0 + p2Br) * 272 + (k0 + p2Bc8) * 2);
                    ldsm4(bh, sb + SCR + off);
                    ldsm4(bl, sb + SCR + B2_LO_OFF + off);
                }
#pragma unroll
                for (int mf = 0; mf < 2; mf++) {
                    mma16816h(acc2[mf][0], ah2[mf], bh[0], bh[1]);
                    mma16816h(acc2[mf][0], ah2[mf], bl[0], bl[1]);
                    mma16816h(acc2[mf][1], ah2[mf], bh[2], bh[3]);
                    mma16816h(acc2[mf][1], ah2[mf], bl[2], bl[3]);
                }
            }
        }
        __syncthreads();   // B2 consumed; SD2/SQT may overwrite

        // stage D2 + Q^T
#pragma unroll
        for (int mf = 0; mf < 2; mf++)
#pragma unroll
            for (int nf = 0; nf < 2; nf++)
#pragma unroll
                for (int h = 0; h < 2; h++) {
                    const int row = R0 + mf * 16 + g + 8 * h;
                    const int col = C2_0 + nf * 8 + 2 * c2;
                    *(float2*)(smf + SCR/4 + row * 68 + col) =
                        make_float2(acc2[mf][nf][2*h], acc2[mf][nf][2*h + 1]);
                }
#pragma unroll
        for (int j = 0; j < 16; j++)
            smf[SCR/4 + SQT_OFF/4 + mrow * 68 + qhalf * 16 + j] = qtv[j];
        __syncthreads();

        // concat write: [q_t, q_tilda, q_t - q_tilda, q_t * q_tilda]
#pragma unroll 4
        for (int mp = 0; mp < 16; mp++) {
            const int mm = mp * 4 + g2;
            float4 qt = *(const float4*)(smf + SCR/4 + SQT_OFF/4 + mm * 68 + j4 * 4);
            float4 td = *(const float4*)(smf + SCR/4 + mm * 68 + j4 * 4);
            float4 o;
            if      (fch == 0) o = qt;
            else if (fch == 1) o = td;
            else if (fch == 2) o = make_float4(qt.x - td.x, qt.y - td.y, qt.z - td.z, qt.w - td.w);
            else               o = make_float4(qt.x * td.x, qt.y * td.y, qt.z * td.z, qt.w * td.w);
            *(float4*)(out + ((size_t)(b * Sn + q0 + mm)) * 2048 + fch * 512 + h0 + j4 * 4) = o;
        }
    }
}

extern "C" void kernel_launch(void* const* d_in, const int* in_sizes, int n_in,
                              void* d_out, int out_size)
{
    const float* Q  = (const float*)d_in[0];
    const float* P  = (const float*)d_in[1];
    const int*   qm = (const int*)d_in[2];
    const int*   pm = (const int*)d_in[3];
    float*       O  = (float*)d_out;

    cudaFuncSetAttribute(rml_mma_kernel,
                         cudaFuncAttributeMaxDynamicSharedMemorySize, SMEM_BYTES);

    rml_mma_kernel<<<1024, 256, SMEM_BYTES>>>(Q, P, qm, pm, O);
}

// round 7
// speedup vs baseline: 2.8651x; 1.0837x over previous
#include <cuda_runtime.h>
#include <cuda_bf16.h>
#include <cuda_fp16.h>
#include <cstdint>

#define NEG_INF_F (-1000000.0f)

constexpr int Hh = 512, Sn = 256;           // H, Sq=Sp
constexpr int TQ = 64;                      // q rows per CTA

// ---- smem byte offsets ----
constexpr int ATT = 0;                      // [64 m][256 k] fp16, row stride 528 = 33792 B
constexpr int SCR = 33792;                  // 43008-byte aliased scratch
//   phase1 (double buffered, 21504/buf): A_hi(16x144) A_lo B_hi(16x528) B_lo
constexpr int P1_ALO = 2304, P1_BHI = 4608, P1_BLO = 13056, P1_BUF = 21504;
//   phase2: B2 chunk [64n][128k] fp16 stride 272 -> 17408 (hi only)
//   epilogue: SD2 float[64][68]=17408, SQT
constexpr int SQT_OFF = 17408;
constexpr int PMNEG = 76800;                // float[256]
constexpr int QMV   = 77824;                // float[64]
constexpr int RED1  = 78080;                // float[64][4]
constexpr int RED2  = 79104;                // float[64][4]
constexpr int SMEM_BYTES = 80128;

__device__ __forceinline__ uint32_t smem_u32(const void* p) {
    uint32_t a;
    asm("{ .reg .u64 t; cvta.to.shared.u64 t, %1; cvt.u32.u64 %0, t; }" : "=r"(a) : "l"(p));
    return a;
}
__device__ __forceinline__ void ldsm4(uint32_t a[4], uint32_t addr) {
    asm volatile("ldmatrix.sync.aligned.m8n8.x4.shared.b16 {%0,%1,%2,%3}, [%4];"
                 : "=r"(a[0]), "=r"(a[1]), "=r"(a[2]), "=r"(a[3]) : "r"(addr));
}
__device__ __forceinline__ void ldsm4t(uint32_t a[4], uint32_t addr) {
    asm volatile("ldmatrix.sync.aligned.m8n8.x4.trans.shared.b16 {%0,%1,%2,%3}, [%4];"
                 : "=r"(a[0]), "=r"(a[1]), "=r"(a[2]), "=r"(a[3]) : "r"(addr));
}
__device__ __forceinline__ void mma16816(float d[4], const uint32_t a[4],
                                         uint32_t b0, uint32_t b1) {
    asm volatile("mma.sync.aligned.m16n8k16.row.col.f32.bf16.bf16.f32 "
                 "{%0,%1,%2,%3}, {%4,%5,%6,%7}, {%8,%9}, {%0,%1,%2,%3};"
                 : "+f"(d[0]), "+f"(d[1]), "+f"(d[2]), "+f"(d[3])
                 : "r"(a[0]), "r"(a[1]), "r"(a[2]), "r"(a[3]), "r"(b0), "r"(b1));
}
__device__ __forceinline__ void mma16816h(float d[4], const uint32_t a[4],
                                          uint32_t b0, uint32_t b1) {
    asm volatile("mma.sync.aligned.m16n8k16.row.col.f32.f16.f16.f32 "
                 "{%0,%1,%2,%3}, {%4,%5,%6,%7}, {%8,%9}, {%0,%1,%2,%3};"
                 : "+f"(d[0]), "+f"(d[1]), "+f"(d[2]), "+f"(d[3])
                 : "r"(a[0]), "r"(a[1]), "r"(a[2]), "r"(a[3]), "r"(b0), "r"(b1));
}
// bf16 2-way split of 4 floats (phase 1)
__device__ __forceinline__ void split4(float4 v, uint2& hi, uint2& lo) {
    __nv_bfloat162 h01 = __float22bfloat162_rn(make_float2(v.x, v.y));
    __nv_bfloat162 h23 = __float22bfloat162_rn(make_float2(v.z, v.w));
    float2 f01 = __bfloat1622float2(h01), f23 = __bfloat1622float2(h23);
    __nv_bfloat162 l01 = __float22bfloat162_rn(make_float2(v.x - f01.x, v.y - f01.y));
    __nv_bfloat162 l23 = __float22bfloat162_rn(make_float2(v.z - f23.x, v.w - f23.y));
    hi.x = *reinterpret_cast<uint32_t*>(&h01); hi.y = *reinterpret_cast<uint32_t*>(&h23);
    lo.x = *reinterpret_cast<uint32_t*>(&l01); lo.y = *reinterpret_cast<uint32_t*>(&l23);
}
// fp16 pack of 4 floats (phase 2 B, single plane)
__device__ __forceinline__ uint2 cvt4h(float4 v) {
    __half2 h01 = __float22half2_rn(make_float2(v.x, v.y));
    __half2 h23 = __float22half2_rn(make_float2(v.z, v.w));
    uint2 r;
    r.x = *reinterpret_cast<uint32_t*>(&h01);
    r.y = *reinterpret_cast<uint32_t*>(&h23);
    return r;
}
__device__ __forceinline__ uint32_t pack2h(float v0, float v1) {
    __half2 h = __float22half2_rn(make_float2(v0, v1));
    return *reinterpret_cast<uint32_t*>(&h);
}

__global__ void __launch_bounds__(256, 2)
rml_mma_kernel(const float* __restrict__ Q, const float* __restrict__ P,
               const int* __restrict__ qmask, const int* __restrict__ pmask,
               float* __restrict__ out)
{
    extern __shared__ char smb[];
    const uint32_t sb = smem_u32(smb);
    float* smf = reinterpret_cast<float*>(smb);

    const int tid = threadIdx.x, lane = tid & 31, wid = tid >> 5;
    const int g = lane >> 2, c2 = lane & 3, sel = lane >> 3, r8 = lane & 7;
    const int wm = wid >> 2, wn = wid & 3;
    const int R0 = wm * 32, C0 = wn * 64;           // phase1 warp tile 32m x 64n
    const int b = blockIdx.x >> 2, q0 = (blockIdx.x & 3) * TQ;

    const float* Qb = Q + (size_t)b * Hh * Sn;
    const float* Pb = P + (size_t)b * Hh * Sn;

    smf[PMNEG/4 + tid] = pmask[b * Sn + tid] ? NEG_INF_F : 0.0f;
    if (tid < 64) smf[QMV/4 + tid] = qmask[b * Sn + q0 + tid] ? 1.0f : 0.0f;

    // lane-constant ldmatrix offsets
    const int arowA = (sel >> 1) * 8 + r8, acol8 = (sel & 1) * 8;   // phase1 A (trans, [k][m])
    const int browB = (sel & 1) * 8 + r8, bcol8 = (sel >> 1) * 8;   // phase1 B (trans, [k][n])
    const int p2Ar  = (sel & 1) * 8 + r8, p2Ac8 = (sel >> 1) * 8;   // phase2 A ([m][k])
    const int p2Br  = (sel >> 1) * 8 + r8, p2Bc8 = (sel & 1) * 8;   // phase2 B ([n][k])

    float acc[2][8][4];
#pragma unroll
    for (int a = 0; a < 2; a++)
#pragma unroll
        for (int c = 0; c < 8; c++)
#pragma unroll
            for (int j = 0; j < 4; j++) acc[a][c][j] = 0.0f;

    // ---------------- Phase 1: sim = Q^T @ P (regs, bf16 3-term) ----------
    {
        int k = tid >> 4, u = tid & 15;
        float4 v = *(const float4*)(Qb + (size_t)k * Sn + q0 + 4 * u);
        uint2 hi, lo; split4(v, hi, lo);
        *(uint2*)(smb + SCR + k * 144 + u * 8) = hi;
        *(uint2*)(smb + SCR + P1_ALO + k * 144 + u * 8) = lo;
#pragma unroll
        for (int i = 0; i < 4; i++) {
            int fl = i * 256 + tid, kk = fl >> 6, uu = fl & 63;
            float4 w = *(const float4*)(Pb + (size_t)kk * Sn + 4 * uu);
            uint2 h2, l2; split4(w, h2, l2);
            *(uint2*)(smb + SCR + P1_BHI + kk * 528 + uu * 8) = h2;
            *(uint2*)(smb + SCR + P1_BLO + kk * 528 + uu * 8) = l2;
        }
    }
    __syncthreads();

    for (int kc = 0; kc < 32; ++kc) {
        const int cur = kc & 1;
        float4 va, vb[4];
        if (kc < 31) {
            const int h0n = (kc + 1) * 16;
            {
                int k = tid >> 4, u = tid & 15;
                va = *(const float4*)(Qb + (size_t)(h0n + k) * Sn + q0 + 4 * u);
            }
#pragma unroll
            for (int i = 0; i < 4; i++) {
                int fl = i * 256 + tid, k = fl >> 6, u = fl & 63;
                vb[i] = *(const float4*)(Pb + (size_t)(h0n + k) * Sn + 4 * u);
            }
        }

        const uint32_t abh = sb + SCR + cur * P1_BUF;
        const uint32_t abl = abh + P1_ALO;
        const uint32_t bbh = sb + SCR + cur * P1_BUF + P1_BHI;
        const uint32_t bbl = sb + SCR + cur * P1_BUF + P1_BLO;

        uint32_t ah[2][4], al[2][4];
#pragma unroll
        for (int mf = 0; mf < 2; mf++) {
            uint32_t off = (uint32_t)(arowA * 144 + (R0 + mf * 16 + acol8) * 2);
            ldsm4t(ah[mf], abh + off);
            ldsm4t(al[mf], abl + off);
        }
#pragma unroll
        for (int nh = 0; nh < 4; nh++) {
            uint32_t off = (uint32_t)(browB * 528 + (C0 + nh * 16 + bcol8) * 2);
            uint32_t bh[4], bl[4];
            ldsm4t(bh, bbh + off);
            ldsm4t(bl, bbl + off);
#pragma unroll
            for (int mf = 0; mf < 2; mf++) {
                mma16816(acc[mf][2*nh],   ah[mf], bh[0], bh[1]);
                mma16816(acc[mf][2*nh],   ah[mf], bl[0], bl[1]);
                mma16816(acc[mf][2*nh],   al[mf], bh[0], bh[1]);
                mma16816(acc[mf][2*nh+1], ah[mf], bh[2], bh[3]);
                mma16816(acc[mf][2*nh+1], ah[mf], bl[2], bl[3]);
                mma16816(acc[mf][2*nh+1], al[mf], bh[2], bh[3]);
            }
        }

        if (kc < 31) {
            const uint32_t base = SCR + (cur ^ 1) * P1_BUF;
            {
                int k = tid >> 4, u = tid & 15;
                uint2 hi, lo; split4(va, hi, lo);
                *(uint2*)(smb + base + k * 144 + u * 8) = hi;
                *(uint2*)(smb + base + P1_ALO + k * 144 + u * 8) = lo;
            }
#pragma unroll
            for (int i = 0; i < 4; i++) {
                int fl = i * 256 + tid, k = fl >> 6, u = fl & 63;
                uint2 hi, lo; split4(vb[i], hi, lo);
                *(uint2*)(smb + base + P1_BHI + k * 528 + u * 8) = hi;
                *(uint2*)(smb + base + P1_BLO + k * 528 + u * 8) = lo;
            }
        }
        __syncthreads();
    }

    // ---------------- Softmax (registers + small smem reduce) -------------
    float pmb[8][2], qv[2][2];
#pragma unroll
    for (int nf = 0; nf < 8; nf++) {
        pmb[nf][0] = smf[PMNEG/4 + C0 + nf * 8 + 2 * c2];
        pmb[nf][1] = smf[PMNEG/4 + C0 + nf * 8 + 2 * c2 + 1];
    }
#pragma unroll
    for (int mf = 0; mf < 2; mf++) {
        qv[mf][0] = smf[QMV/4 + R0 + mf * 16 + g];
        qv[mf][1] = smf[QMV/4 + R0 + mf * 16 + g + 8];
    }
#pragma unroll
    for (int mf = 0; mf < 2; mf++)
#pragma unroll
        for (int h = 0; h < 2; h++) {
            float m = -3.4e38f;
#pragma unroll
            for (int nf = 0; nf < 8; nf++)
#pragma unroll
                for (int p = 0; p < 2; p++) {
                    float x = acc[mf][nf][2*h + p] + qv[mf][h] * pmb[nf][p];
                    acc[mf][nf][2*h + p] = x;
                    m = fmaxf(m, x);
                }
            m = fmaxf(m, __shfl_xor_sync(0xffffffffu, m, 1));
            m = fmaxf(m, __shfl_xor_sync(0xffffffffu, m, 2));
            if (c2 == 0) smf[RED1/4 + (R0 + mf * 16 + g + 8 * h) * 4 + wn] = m;
        }
    __syncthreads();
#pragma unroll
    for (int mf = 0; mf < 2; mf++)
#pragma unroll
        for (int h = 0; h < 2; h++) {
            const int row = R0 + mf * 16 + g + 8 * h;
            float m = fmaxf(fmaxf(smf[RED1/4 + row*4], smf[RED1/4 + row*4 + 1]),
                            fmaxf(smf[RED1/4 + row*4 + 2], smf[RED1/4 + row*4 + 3]));
            float s = 0.0f;
#pragma unroll
            for (int nf = 0; nf < 8; nf++)
#pragma unroll
                for (int p = 0; p < 2; p++) {
                    float e = __expf(acc[mf][nf][2*h + p] - m);
                    acc[mf][nf][2*h + p] = e;
                    s += e;
                }
            s += __shfl_xor_sync(0xffffffffu, s, 1);
            s += __shfl_xor_sync(0xffffffffu, s, 2);
            if (c2 == 0) smf[RED2/4 + row * 4 + wn] = s;
        }
    __syncthreads();
#pragma unroll
    for (int mf = 0; mf < 2; mf++)
#pragma unroll
        for (int h = 0; h < 2; h++) {
            const int row = R0 + mf * 16 + g + 8 * h;
            float s = smf[RED2/4 + row*4] + smf[RED2/4 + row*4 + 1] +
                      smf[RED2/4 + row*4 + 2] + smf[RED2/4 + row*4 + 3];
            const float inv = 1.0f / s;
#pragma unroll
            for (int nf = 0; nf < 8; nf++) {
                float v0 = acc[mf][nf][2*h]     * inv;
                float v1 = acc[mf][nf][2*h + 1] * inv;
                uint32_t off = (uint32_t)(row * 528 + (C0 + nf * 8 + 2 * c2) * 2);
                *(uint32_t*)(smb + ATT + off) = pack2h(v0, v1);   // fp16 attention
            }
        }

    // -------- Phase 2: q_tilda = att @ P^T (fp16 att x fp16 P) ------------
    const int C2_0 = wn * 16;            // 16 h cols per warp per tile
    const int j4 = tid & 15, fch = (tid >> 4) & 3, g2 = tid >> 6;   // g2 0..3
    const int mrow = tid & 63, qhalf = tid >> 6;                    // 0..3

    // prefetch tile0/chunk0: B2 [64n][128k] (8 float4/thread)
    float4 vb2[8];
#pragma unroll
    for (int i = 0; i < 8; i++) {
        int fl = i * 256 + tid, n = fl >> 5, u = fl & 31;
        vb2[i] = *(const float4*)(Pb + (size_t)n * Sn + 4 * u);
    }

    for (int t = 0; t < 8; ++t) {
        const int h0 = t * 64;
        float acc2[2][2][4];
#pragma unroll
        for (int a = 0; a < 2; a++)
#pragma unroll
            for (int c = 0; c < 2; c++)
#pragma unroll
                for (int j = 0; j < 4; j++) acc2[a][c][j] = 0.0f;

        float qtv[16];

#pragma unroll 1
        for (int cch = 0; cch < 2; ++cch) {
            __syncthreads();   // scratch free (prior readers done)
            // stage current B2 chunk from prefetch regs (fp16, single plane)
#pragma unroll
            for (int i = 0; i < 8; i++) {
                int fl = i * 256 + tid, n = fl >> 5, u = fl & 31;
                *(uint2*)(smb + SCR + n * 272 + u * 8) = cvt4h(vb2[i]);
            }
            // prefetch next chunk: (t, k=128) or (t+1, k=0)
            if (cch == 0 || t < 7) {
                const int h0n = (cch == 0) ? h0 : h0 + 64;
                const int k0n = (cch == 0) ? 128 : 0;
#pragma unroll
                for (int i = 0; i < 8; i++) {
                    int fl = i * 256 + tid, n = fl >> 5, u = fl & 31;
                    vb2[i] = *(const float4*)(Pb + (size_t)(h0n + n) * Sn + k0n + 4 * u);
                }
            }
            if (cch == 0) {   // overlap Q^T loads with both chunks' MMAs
#pragma unroll
                for (int j = 0; j < 16; j++)
                    qtv[j] = Qb[(size_t)(h0 + qhalf * 16 + j) * Sn + q0 + mrow];
            }
            __syncthreads();

            const int kg = cch * 128;
#pragma unroll 2
            for (int ks = 0; ks < 8; ++ks) {
                const int k0 = ks * 16;
                uint32_t ah2[2][4];
#pragma unroll
                for (int mf = 0; mf < 2; mf++) {
                    uint32_t off = (uint32_t)((R0 + mf * 16 + p2Ar) * 528 + (kg + k0 + p2Ac8) * 2);
                    ldsm4(ah2[mf], sb + ATT + off);
                }
                uint32_t bh[4];
                {
                    uint32_t off = (uint32_t)((C2_0 + p2Br) * 272 + (k0 + p2Bc8) * 2);
                    ldsm4(bh, sb + SCR + off);
                }
#pragma unroll
                for (int mf = 0; mf < 2; mf++) {
                    mma16816h(acc2[mf][0], ah2[mf], bh[0], bh[1]);
                    mma16816h(acc2[mf][1], ah2[mf], bh[2], bh[3]);
                }
            }
        }
        __syncthreads();   // B2 consumed; SD2/SQT may overwrite

        // stage D2 + Q^T
#pragma unroll
        for (int mf = 0; mf < 2; mf++)
#pragma unroll
            for (int nf = 0; nf < 2; nf++)
#pragma unroll
                for (int h = 0; h < 2; h++) {
                    const int row = R0 + mf * 16 + g + 8 * h;
                    const int col = C2_0 + nf * 8 + 2 * c2;
                    *(float2*)(smf + SCR/4 + row * 68 + col) =
                        make_float2(acc2[mf][nf][2*h], acc2[mf][nf][2*h + 1]);
                }
#pragma unroll
        for (int j = 0; j < 16; j++)
            smf[SCR/4 + SQT_OFF/4 + mrow * 68 + qhalf * 16 + j] = qtv[j];
        __syncthreads();

        // concat write: [q_t, q_tilda, q_t - q_tilda, q_t * q_tilda]
#pragma unroll 4
        for (int mp = 0; mp < 16; mp++) {
            const int mm = mp * 4 + g2;
            float4 qt = *(const float4*)(smf + SCR/4 + SQT_OFF/4 + mm * 68 + j4 * 4);
            float4 td = *(const float4*)(smf + SCR/4 + mm * 68 + j4 * 4);
            float4 o;
            if      (fch == 0) o = qt;
            else if (fch == 1) o = td;
            else if (fch == 2) o = make_float4(qt.x - td.x, qt.y - td.y, qt.z - td.z, qt.w - td.w);
            else               o = make_float4(qt.x * td.x, qt.y * td.y, qt.z * td.z, qt.w * td.w);
            *(float4*)(out + ((size_t)(b * Sn + q0 + mm)) * 2048 + fch * 512 + h0 + j4 * 4) = o;
        }
    }
}

extern "C" void kernel_launch(void* const* d_in, const int* in_sizes, int n_in,
                              void* d_out, int out_size)
{
    const float* Q  = (const float*)d_in[0];
    const float* P  = (const float*)d_in[1];
    const int*   qm = (const int*)d_in[2];
    const int*   pm = (const int*)d_in[3];
    float*       O  = (float*)d_out;

    cudaFuncSetAttribute(rml_mma_kernel,
                         cudaFuncAttributeMaxDynamicSharedMemorySize, SMEM_BYTES);

    rml_mma_kernel<<<1024, 256, SMEM_BYTES>>>(Q, P, qm, pm, O);
}

// round 10
// speedup vs baseline: 2.9177x; 1.0183x over previous
#include <cuda_runtime.h>
#include <cuda_bf16.h>
#include <cuda_fp16.h>
#include <cstdint>

#define NEG_INF_F (-1000000.0f)

constexpr int Hh = 512, Sn = 256;           // H, Sq=Sp
constexpr int TQ = 64;                      // q rows per CTA

// ---- smem byte offsets ----
constexpr int ATT = 0;                      // [64 m][256 k] fp16, row stride 528 = 33792 B
constexpr int SCR = 33792;                  // 34816-byte aliased scratch
//   phase1 (double buffered, 13056/buf): A_hi(16x144) A_lo(16x144) B(16x528)
constexpr int P1_ALO = 2304, P1_B = 4608, P1_BUF = 13056;
//   phase2: B2 chunk [64n][128k] fp16 stride 272 -> 17408 (single plane)
//   epilogue: SD2 float[64][68]=17408 at SCR, SQT at SCR+17408
constexpr int SQT_OFF = 17408;
constexpr int PMNEG = 68608;                // float[256]
constexpr int QMV   = 69632;                // float[64]
constexpr int RED1  = 69888;                // float[64][4]
constexpr int RED2  = 70912;                // float[64][4]
constexpr int SMEM_BYTES = 71936;

__device__ __forceinline__ uint32_t smem_u32(const void* p) {
    uint32_t a;
    asm("{ .reg .u64 t; cvta.to.shared.u64 t, %1; cvt.u32.u64 %0, t; }" : "=r"(a) : "l"(p));
    return a;
}
__device__ __forceinline__ void ldsm4(uint32_t a[4], uint32_t addr) {
    asm volatile("ldmatrix.sync.aligned.m8n8.x4.shared.b16 {%0,%1,%2,%3}, [%4];"
                 : "=r"(a[0]), "=r"(a[1]), "=r"(a[2]), "=r"(a[3]) : "r"(addr));
}
__device__ __forceinline__ void ldsm4t(uint32_t a[4], uint32_t addr) {
    asm volatile("ldmatrix.sync.aligned.m8n8.x4.trans.shared.b16 {%0,%1,%2,%3}, [%4];"
                 : "=r"(a[0]), "=r"(a[1]), "=r"(a[2]), "=r"(a[3]) : "r"(addr));
}
__device__ __forceinline__ void mma16816h(float d[4], const uint32_t a[4],
                                          uint32_t b0, uint32_t b1) {
    asm volatile("mma.sync.aligned.m16n8k16.row.col.f32.f16.f16.f32 "
                 "{%0,%1,%2,%3}, {%4,%5,%6,%7}, {%8,%9}, {%0,%1,%2,%3};"
                 : "+f"(d[0]), "+f"(d[1]), "+f"(d[2]), "+f"(d[3])
                 : "r"(a[0]), "r"(a[1]), "r"(a[2]), "r"(a[3]), "r"(b0), "r"(b1));
}
// fp16 pack of 4 floats (single plane)
__device__ __forceinline__ uint2 cvt4h(float4 v) {
    __half2 h01 = __float22half2_rn(make_float2(v.x, v.y));
    __half2 h23 = __float22half2_rn(make_float2(v.z, v.w));
    uint2 r;
    r.x = *reinterpret_cast<uint32_t*>(&h01);
    r.y = *reinterpret_cast<uint32_t*>(&h23);
    return r;
}
// fp16 2-way split of 4 floats (phase-1 Q)
__device__ __forceinline__ void split4h(float4 v, uint2& hi, uint2& lo) {
    __half2 h01 = __float22half2_rn(make_float2(v.x, v.y));
    __half2 h23 = __float22half2_rn(make_float2(v.z, v.w));
    float2 f01 = __half22float2(h01), f23 = __half22float2(h23);
    __half2 l01 = __float22half2_rn(make_float2(v.x - f01.x, v.y - f01.y));
    __half2 l23 = __float22half2_rn(make_float2(v.z - f23.x, v.w - f23.y));
    hi.x = *reinterpret_cast<uint32_t*>(&h01); hi.y = *reinterpret_cast<uint32_t*>(&h23);
    lo.x = *reinterpret_cast<uint32_t*>(&l01); lo.y = *reinterpret_cast<uint32_t*>(&l23);
}
__device__ __forceinline__ uint32_t pack2h(float v0, float v1) {
    __half2 h = __float22half2_rn(make_float2(v0, v1));
    return *reinterpret_cast<uint32_t*>(&h);
}

__global__ void __launch_bounds__(256, 2)
rml_mma_kernel(const float* __restrict__ Q, const float* __restrict__ P,
               const int* __restrict__ qmask, const int* __restrict__ pmask,
               float* __restrict__ out)
{
    extern __shared__ char smb[];
    const uint32_t sb = smem_u32(smb);
    float* smf = reinterpret_cast<float*>(smb);

    const int tid = threadIdx.x, lane = tid & 31, wid = tid >> 5;
    const int g = lane >> 2, c2 = lane & 3, sel = lane >> 3, r8 = lane & 7;
    const int wm = wid >> 2, wn = wid & 3;
    const int R0 = wm * 32, C0 = wn * 64;           // phase1 warp tile 32m x 64n
    const int b = blockIdx.x >> 2, q0 = (blockIdx.x & 3) * TQ;

    const float* Qb = Q + (size_t)b * Hh * Sn;
    const float* Pb = P + (size_t)b * Hh * Sn;

    smf[PMNEG/4 + tid] = pmask[b * Sn + tid] ? NEG_INF_F : 0.0f;
    if (tid < 64) smf[QMV/4 + tid] = qmask[b * Sn + q0 + tid] ? 1.0f : 0.0f;

    // lane-constant ldmatrix offsets
    const int arowA = (sel >> 1) * 8 + r8, acol8 = (sel & 1) * 8;   // phase1 A (trans, [k][m])
    const int browB = (sel & 1) * 8 + r8, bcol8 = (sel >> 1) * 8;   // phase1 B (trans, [k][n])
    const int p2Ar  = (sel & 1) * 8 + r8, p2Ac8 = (sel >> 1) * 8;   // phase2 A ([m][k])
    const int p2Br  = (sel >> 1) * 8 + r8, p2Bc8 = (sel & 1) * 8;   // phase2 B ([n][k])

    float acc[2][8][4];
#pragma unroll
    for (int a = 0; a < 2; a++)
#pragma unroll
        for (int c = 0; c < 8; c++)
#pragma unroll
            for (int j = 0; j < 4; j++) acc[a][c][j] = 0.0f;

    // -------- Phase 1: sim = Q^T @ P (Q split fp16 hi/lo, P fp16) ---------
    {
        int k = tid >> 4, u = tid & 15;
        float4 v = *(const float4*)(Qb + (size_t)k * Sn + q0 + 4 * u);
        uint2 hi, lo; split4h(v, hi, lo);
        *(uint2*)(smb + SCR + k * 144 + u * 8) = hi;
        *(uint2*)(smb + SCR + P1_ALO + k * 144 + u * 8) = lo;
#pragma unroll
        for (int i = 0; i < 4; i++) {
            int fl = i * 256 + tid, kk = fl >> 6, uu = fl & 63;
            float4 w = *(const float4*)(Pb + (size_t)kk * Sn + 4 * uu);
            *(uint2*)(smb + SCR + P1_B + kk * 528 + uu * 8) = cvt4h(w);
        }
    }
    __syncthreads();

    for (int kc = 0; kc < 32; ++kc) {
        const int cur = kc & 1;
        float4 va, vb[4];
        if (kc < 31) {
            const int h0n = (kc + 1) * 16;
            {
                int k = tid >> 4, u = tid & 15;
                va = *(const float4*)(Qb + (size_t)(h0n + k) * Sn + q0 + 4 * u);
            }
#pragma unroll
            for (int i = 0; i < 4; i++) {
                int fl = i * 256 + tid, k = fl >> 6, u = fl & 63;
                vb[i] = *(const float4*)(Pb + (size_t)(h0n + k) * Sn + 4 * u);
            }
        }

        const uint32_t abh = sb + SCR + cur * P1_BUF;
        const uint32_t abl = abh + P1_ALO;
        const uint32_t bbuf = sb + SCR + cur * P1_BUF + P1_B;

        uint32_t ah[2][4], al[2][4];
#pragma unroll
        for (int mf = 0; mf < 2; mf++) {
            uint32_t off = (uint32_t)(arowA * 144 + (R0 + mf * 16 + acol8) * 2);
            ldsm4t(ah[mf], abh + off);
            ldsm4t(al[mf], abl + off);
        }
#pragma unroll
        for (int nh = 0; nh < 4; nh++) {
            uint32_t off = (uint32_t)(browB * 528 + (C0 + nh * 16 + bcol8) * 2);
            uint32_t bh[4];
            ldsm4t(bh, bbuf + off);
#pragma unroll
            for (int mf = 0; mf < 2; mf++) {
                mma16816h(acc[mf][2*nh],   ah[mf], bh[0], bh[1]);
                mma16816h(acc[mf][2*nh],   al[mf], bh[0], bh[1]);
                mma16816h(acc[mf][2*nh+1], ah[mf], bh[2], bh[3]);
                mma16816h(acc[mf][2*nh+1], al[mf], bh[2], bh[3]);
            }
        }

        if (kc < 31) {
            const uint32_t base = SCR + (cur ^ 1) * P1_BUF;
            {
                int k = tid >> 4, u = tid & 15;
                uint2 hi, lo; split4h(va, hi, lo);
                *(uint2*)(smb + base + k * 144 + u * 8) = hi;
                *(uint2*)(smb + base + P1_ALO + k * 144 + u * 8) = lo;
            }
#pragma unroll
            for (int i = 0; i < 4; i++) {
                int fl = i * 256 + tid, k = fl >> 6, u = fl & 63;
                *(uint2*)(smb + base + P1_B + k * 528 + u * 8) = cvt4h(vb[i]);
            }
        }
        __syncthreads();
    }

    // ---------------- Softmax (registers + small smem reduce) -------------
    float pmb[8][2], qv[2][2];
#pragma unroll
    for (int nf = 0; nf < 8; nf++) {
        pmb[nf][0] = smf[PMNEG/4 + C0 + nf * 8 + 2 * c2];
        pmb[nf][1] = smf[PMNEG/4 + C0 + nf * 8 + 2 * c2 + 1];
    }
#pragma unroll
    for (int mf = 0; mf < 2; mf++) {
        qv[mf][0] = smf[QMV/4 + R0 + mf * 16 + g];
        qv[mf][1] = smf[QMV/4 + R0 + mf * 16 + g + 8];
    }
#pragma unroll
    for (int mf = 0; mf < 2; mf++)
#pragma unroll
        for (int h = 0; h < 2; h++) {
            float m = -3.4e38f;
#pragma unroll
            for (int nf = 0; nf < 8; nf++)
#pragma unroll
                for (int p = 0; p < 2; p++) {
                    float x = acc[mf][nf][2*h + p] + qv[mf][h] * pmb[nf][p];
                    acc[mf][nf][2*h + p] = x;
                    m = fmaxf(m, x);
                }
            m = fmaxf(m, __shfl_xor_sync(0xffffffffu, m, 1));
            m = fmaxf(m, __shfl_xor_sync(0xffffffffu, m, 2));
            if (c2 == 0) smf[RED1/4 + (R0 + mf * 16 + g + 8 * h) * 4 + wn] = m;
        }
    __syncthreads();
#pragma unroll
    for (int mf = 0; mf < 2; mf++)
#pragma unroll
        for (int h = 0; h < 2; h++) {
            const int row = R0 + mf * 16 + g + 8 * h;
            float m = fmaxf(fmaxf(smf[RED1/4 + row*4], smf[RED1/4 + row*4 + 1]),
                            fmaxf(smf[RED1/4 + row*4 + 2], smf[RED1/4 + row*4 + 3]));
            float s = 0.0f;
#pragma unroll
            for (int nf = 0; nf < 8; nf++)
#pragma unroll
                for (int p = 0; p < 2; p++) {
                    float e = __expf(acc[mf][nf][2*h + p] - m);
                    acc[mf][nf][2*h + p] = e;
                    s += e;
                }
            s += __shfl_xor_sync(0xffffffffu, s, 1);
            s += __shfl_xor_sync(0xffffffffu, s, 2);
            if (c2 == 0) smf[RED2/4 + row * 4 + wn] = s;
        }
    __syncthreads();
#pragma unroll
    for (int mf = 0; mf < 2; mf++)
#pragma unroll
        for (int h = 0; h < 2; h++) {
            const int row = R0 + mf * 16 + g + 8 * h;
            float s = smf[RED2/4 + row*4] + smf[RED2/4 + row*4 + 1] +
                      smf[RED2/4 + row*4 + 2] + smf[RED2/4 + row*4 + 3];
            const float inv = 1.0f / s;
#pragma unroll
            for (int nf = 0; nf < 8; nf++) {
                float v0 = acc[mf][nf][2*h]     * inv;
                float v1 = acc[mf][nf][2*h + 1] * inv;
                uint32_t off = (uint32_t)(row * 528 + (C0 + nf * 8 + 2 * c2) * 2);
                *(uint32_t*)(smb + ATT + off) = pack2h(v0, v1);   // fp16 attention
            }
        }

    // -------- Phase 2: q_tilda = att @ P^T (fp16 att x fp16 P) ------------
    const int C2_0 = wn * 16;            // 16 h cols per warp per tile
    const int j4 = tid & 15, fch = (tid >> 4) & 3, g2 = tid >> 6;   // g2 0..3
    const int mrow = tid & 63, qhalf = tid >> 6;                    // 0..3

    // prefetch tile0/chunk0: B2 [64n][128k] (8 float4/thread)
    float4 vb2[8];
#pragma unroll
    for (int i = 0; i < 8; i++) {
        int fl = i * 256 + tid, n = fl >> 5, u = fl & 31;
        vb2[i] = *(const float4*)(Pb + (size_t)n * Sn + 4 * u);
    }

    for (int t = 0; t < 8; ++t) {
        const int h0 = t * 64;
        float acc2[2][2][4];
#pragma unroll
        for (int a = 0; a < 2; a++)
#pragma unroll
            for (int c = 0; c < 2; c++)
#pragma unroll
                for (int j = 0; j < 4; j++) acc2[a][c][j] = 0.0f;

        float qtv[16];

#pragma unroll 1
        for (int cch = 0; cch < 2; ++cch) {
            __syncthreads();   // scratch free (prior readers done)
            // stage current B2 chunk from prefetch regs (fp16, single plane)
#pragma unroll
            for (int i = 0; i < 8; i++) {
                int fl = i * 256 + tid, n = fl >> 5, u = fl & 31;
                *(uint2*)(smb + SCR + n * 272 + u * 8) = cvt4h(vb2[i]);
            }
            // prefetch next chunk: (t, k=128) or (t+1, k=0)
            if (cch == 0 || t < 7) {
                const int h0n = (cch == 0) ? h0 : h0 + 64;
                const int k0n = (cch == 0) ? 128 : 0;
#pragma unroll
                for (int i = 0; i < 8; i++) {
                    int fl = i * 256 + tid, n = fl >> 5, u = fl & 31;
                    vb2[i] = *(const float4*)(Pb + (size_t)(h0n + n) * Sn + k0n + 4 * u);
                }
            }
            if (cch == 0) {   // overlap Q^T loads with both chunks' MMAs
#pragma unroll
                for (int j = 0; j < 16; j++)
                    qtv[j] = Qb[(size_t)(h0 + qhalf * 16 + j) * Sn + q0 + mrow];
            }
            __syncthreads();

            const int kg = cch * 128;
#pragma unroll 2
            for (int ks = 0; ks < 8; ++ks) {
                const int k0 = ks * 16;
                uint32_t ah2[2][4];
#pragma unroll
                for (int mf = 0; mf < 2; mf++) {
                    uint32_t off = (uint32_t)((R0 + mf * 16 + p2Ar) * 528 + (kg + k0 + p2Ac8) * 2);
                    ldsm4(ah2[mf], sb + ATT + off);
                }
                uint32_t bh[4];
                {
                    uint32_t off = (uint32_t)((C2_0 + p2Br) * 272 + (k0 + p2Bc8) * 2);
                    ldsm4(bh, sb + SCR + off);
                }
#pragma unroll
                for (int mf = 0; mf < 2; mf++) {
                    mma16816h(acc2[mf][0], ah2[mf], bh[0], bh[1]);
                    mma16816h(acc2[mf][1], ah2[mf], bh[2], bh[3]);
                }
            }
        }
        __syncthreads();   // B2 consumed; SD2/SQT may overwrite

        // stage D2 + Q^T
#pragma unroll
        for (int mf = 0; mf < 2; mf++)
#pragma unroll
            for (int nf = 0; nf < 2; nf++)
#pragma unroll
                for (int h = 0; h < 2; h++) {
                    const int row = R0 + mf * 16 + g + 8 * h;
                    const int col = C2_0 + nf * 8 + 2 * c2;
                    *(float2*)(smf + SCR/4 + row * 68 + col) =
                        make_float2(acc2[mf][nf][2*h], acc2[mf][nf][2*h + 1]);
                }
#pragma unroll
        for (int j = 0; j < 16; j++)
            smf[SCR/4 + SQT_OFF/4 + mrow * 68 + qhalf * 16 + j] = qtv[j];
        __syncthreads();

        // concat write: [q_t, q_tilda, q_t - q_tilda, q_t * q_tilda]
#pragma unroll 4
        for (int mp = 0; mp < 16; mp++) {
            const int mm = mp * 4 + g2;
            float4 qt = *(const float4*)(smf + SCR/4 + SQT_OFF/4 + mm * 68 + j4 * 4);
            float4 td = *(const float4*)(smf + SCR/4 + mm * 68 + j4 * 4);
            float4 o;
            if      (fch == 0) o = qt;
            else if (fch == 1) o = td;
            else if (fch == 2) o = make_float4(qt.x - td.x, qt.y - td.y, qt.z - td.z, qt.w - td.w);
            else               o = make_float4(qt.x * td.x, qt.y * td.y, qt.z * td.z, qt.w * td.w);
            *(float4*)(out + ((size_t)(b * Sn + q0 + mm)) * 2048 + fch * 512 + h0 + j4 * 4) = o;
        }
    }
}

extern "C" void kernel_launch(void* const* d_in, const int* in_sizes, int n_in,
                              void* d_out, int out_size)
{
    const float* Q  = (const float*)d_in[0];
    const float* P  = (const float*)d_in[1];
    const int*   qm = (const int*)d_in[2];
    const int*   pm = (const int*)d_in[3];
    float*       O  = (float*)d_out;

    cudaFuncSetAttribute(rml_mma_kernel,
                         cudaFuncAttributeMaxDynamicSharedMemorySize, SMEM_BYTES);

    rml_mma_kernel<<<1024, 256, SMEM_BYTES>>>(Q, P, qm, pm, O);
}